// round 12
// baseline (speedup 1.0000x reference)
#include <cuda_runtime.h>
#include <cuda_bf16.h>
#include <cuda_fp16.h>
#include <cstdint>

// ================= scratch (no allocations allowed) =================
__device__ __align__(256) __half g_qkvh[8192 * 2304], g_qkvl[8192 * 2304]; // q|k|v fp16 hi/lo
__device__ __align__(256) __half g_kv2h[8192 * 1536], g_kv2l[8192 * 1536]; // k2|v2 fp16 hi/lo

__device__ __align__(256) __nv_bfloat16 g_xhi[8192 * 768],  g_xlo[8192 * 768];
__device__ __align__(256) __nv_bfloat16 g_x2hi[8192 * 768], g_x2lo[8192 * 768];
__device__ __align__(256) __nv_bfloat16 g_wqhi[2304 * 768], g_wqlo[2304 * 768];
__device__ __align__(256) __nv_bfloat16 g_wphi[768 * 768],  g_wplo[768 * 768];
__device__ __align__(256) __nv_bfloat16 g_o1hi[8192 * 768], g_o1lo[8192 * 768];
__device__ __align__(256) __nv_bfloat16 g_o2hi[8192 * 768], g_o2lo[8192 * 768];

// ================= helpers =================
__device__ __forceinline__ void cp16(uint32_t s, const void* g) {
    asm volatile("cp.async.cg.shared.global [%0], [%1], 16;" :: "r"(s), "l"(g));
}

__device__ __forceinline__ void ldsm4(uint32_t* r, uint32_t addr) {
    asm volatile("ldmatrix.sync.aligned.m8n8.x4.shared.b16 {%0,%1,%2,%3}, [%4];"
                 : "=r"(r[0]), "=r"(r[1]), "=r"(r[2]), "=r"(r[3]) : "r"(addr));
}

__device__ __forceinline__ void ldsm4t(uint32_t* r, uint32_t addr) {
    asm volatile("ldmatrix.sync.aligned.m8n8.x4.trans.shared.b16 {%0,%1,%2,%3}, [%4];"
                 : "=r"(r[0]), "=r"(r[1]), "=r"(r[2]), "=r"(r[3]) : "r"(addr));
}

__device__ __forceinline__ void mma16816(float* c, const uint32_t* a,
                                         uint32_t b0, uint32_t b1) {
    asm volatile(
        "mma.sync.aligned.m16n8k16.row.col.f32.bf16.bf16.f32 "
        "{%0,%1,%2,%3}, {%4,%5,%6,%7}, {%8,%9}, {%0,%1,%2,%3};"
        : "+f"(c[0]), "+f"(c[1]), "+f"(c[2]), "+f"(c[3])
        : "r"(a[0]), "r"(a[1]), "r"(a[2]), "r"(a[3]), "r"(b0), "r"(b1));
}

__device__ __forceinline__ void mma_f16(float* c, const uint32_t* a,
                                        uint32_t b0, uint32_t b1) {
    asm volatile(
        "mma.sync.aligned.m16n8k16.row.col.f32.f16.f16.f32 "
        "{%0,%1,%2,%3}, {%4,%5,%6,%7}, {%8,%9}, {%0,%1,%2,%3};"
        : "+f"(c[0]), "+f"(c[1]), "+f"(c[2]), "+f"(c[3])
        : "r"(a[0]), "r"(a[1]), "r"(a[2]), "r"(a[3]), "r"(b0), "r"(b1));
}

__device__ __forceinline__ uint32_t h2u(__half2 h) { return *(uint32_t*)&h; }

// ================= bf16 hi/lo split =================
__global__ __launch_bounds__(256)
void split_bf16(const float4* __restrict__ src, uint2* __restrict__ hi,
                uint2* __restrict__ lo, int n4)
{
    int i = blockIdx.x * blockDim.x + threadIdx.x;
    if (i >= n4) return;
    float4 v = src[i];
    float f[4] = {v.x, v.y, v.z, v.w};
    uint32_t h[4], l[4];
#pragma unroll
    for (int j = 0; j < 4; j++) {
        __nv_bfloat16 hb = __float2bfloat16_rn(f[j]);
        float r = f[j] - __bfloat162float(hb);
        __nv_bfloat16 lb = __float2bfloat16_rn(r);
        h[j] = (uint32_t)__bfloat16_as_ushort(hb);
        l[j] = (uint32_t)__bfloat16_as_ushort(lb);
    }
    hi[i] = make_uint2(h[0] | (h[1] << 16), h[2] | (h[3] << 16));
    lo[i] = make_uint2(l[0] | (l[1] << 16), l[2] | (l[3] << 16));
}

// ================= HMMA bf16x3 GEMM: 128x128 tile, 512 thr, 3-stage =========
// Two A-streams in one launch: bx < nx1 -> stream 1, else stream 2.
#define G3_AH 0
#define G3_AL 16384
#define G3_BH 32768
#define G3_BL 49152
#define G3_STAGE 65536
#define GEMM_SMEM (3 * G3_STAGE)

__global__ __launch_bounds__(512, 1)
void gemm_hmma(const __nv_bfloat16* __restrict__ A1hi, const __nv_bfloat16* __restrict__ A1lo,
               const __nv_bfloat16* __restrict__ A2hi, const __nv_bfloat16* __restrict__ A2lo,
               const __nv_bfloat16* __restrict__ Bhi, const __nv_bfloat16* __restrict__ Blo,
               float* __restrict__ C1, float* __restrict__ C2, const float* __restrict__ bias,
               __half* __restrict__ H1h, __half* __restrict__ H1l,
               __half* __restrict__ H2h, __half* __restrict__ H2l,
               int nx1, int N1, int N2, int woff2, int mode)
{
    extern __shared__ __align__(1024) char smem[];
    const uint32_t sb = (uint32_t)__cvta_generic_to_shared(smem);
    const int t = threadIdx.x;
    const int wid = t >> 5, lane = t & 31;
    const int m0 = blockIdx.y * 128;
    const int K = 768, NC = 12;

    const int s2 = (int)blockIdx.x >= nx1;
    const int bx = s2 ? (int)blockIdx.x - nx1 : (int)blockIdx.x;
    const int n0 = bx * 128;
    const int N = s2 ? N2 : N1;
    const int woff = s2 ? woff2 : 0;

    const int warp_m = (wid >> 2) * 32;
    const int warp_n = (wid & 3) * 32;

    float acc[2][4][4];
#pragma unroll
    for (int i = 0; i < 2; i++)
#pragma unroll
        for (int j = 0; j < 4; j++)
#pragma unroll
            for (int v = 0; v < 4; v++) acc[i][j][v] = 0.f;

    const __nv_bfloat16* Ah = (s2 ? A2hi : A1hi) + (size_t)m0 * K;
    const __nv_bfloat16* Al = (s2 ? A2lo : A1lo) + (size_t)m0 * K;
    const __nv_bfloat16* Bh = Bhi + (size_t)(woff + n0) * K;
    const __nv_bfloat16* Bl = Blo + (size_t)(woff + n0) * K;

    auto load_chunk = [&](int c, int st) {
        const int kc = c * 64;
        const uint32_t base = sb + st * G3_STAGE;
#pragma unroll
        for (int i = 0; i < 2; i++) {            // 1024 granules per tile, 2/thread
            const int gi = t + i * 512;
            const int row = gi >> 3, g = gi & 7;
            const uint32_t loff = (uint32_t)(row * 128 + ((g ^ (row & 7)) << 4));
            const size_t goff = (size_t)row * K + kc + g * 8;
            cp16(base + G3_AH + loff, Ah + goff);
            cp16(base + G3_AL + loff, Al + goff);
            cp16(base + G3_BH + loff, Bh + goff);
            cp16(base + G3_BL + loff, Bl + goff);
        }
        asm volatile("cp.async.commit_group;");
    };

    const int fr   = lane & 15;
    const int half = lane >> 4;
    const int arow = warp_m + fr;
    const int brow = warp_n + fr;
    const int aswz = arow & 7;
    const int bswz = brow & 7;
    const uint32_t arow_off = (uint32_t)(arow * 128);
    const uint32_t brow_off = (uint32_t)(brow * 128);

    load_chunk(0, 0);
    load_chunk(1, 1);

    for (int c = 0; c < NC; ++c) {
        const int st = c % 3;
        if (c + 2 < NC) {
            load_chunk(c + 2, (c + 2) % 3);
            asm volatile("cp.async.wait_group 2;");
        } else if (c + 1 < NC) {
            asm volatile("cp.async.wait_group 1;");
        } else {
            asm volatile("cp.async.wait_group 0;");
        }
        __syncthreads();

        const uint32_t base = sb + st * G3_STAGE;
#pragma unroll
        for (int kk = 0; kk < 4; kk++) {
            const int kg = kk * 2 + half;
            const uint32_t aoff = arow_off + (uint32_t)((kg ^ aswz) << 4);
            const uint32_t boff = brow_off + (uint32_t)((kg ^ bswz) << 4);

            uint32_t ah[2][4], al[2][4], bh[2][4], bl[2][4];
#pragma unroll
            for (int mi = 0; mi < 2; mi++) {
                ldsm4(ah[mi], base + G3_AH + aoff + mi * (16 * 128));
                ldsm4(al[mi], base + G3_AL + aoff + mi * (16 * 128));
            }
#pragma unroll
            for (int bj = 0; bj < 2; bj++) {
                ldsm4(bh[bj], base + G3_BH + boff + bj * (16 * 128));
                ldsm4(bl[bj], base + G3_BL + boff + bj * (16 * 128));
            }
#pragma unroll
            for (int mi = 0; mi < 2; mi++)
#pragma unroll
                for (int bj = 0; bj < 2; bj++) {
                    mma16816(acc[mi][bj * 2],     ah[mi], bh[bj][0], bh[bj][2]);
                    mma16816(acc[mi][bj * 2 + 1], ah[mi], bh[bj][1], bh[bj][3]);
                }
#pragma unroll
            for (int mi = 0; mi < 2; mi++)
#pragma unroll
                for (int bj = 0; bj < 2; bj++) {
                    mma16816(acc[mi][bj * 2],     ah[mi], bl[bj][0], bl[bj][2]);
                    mma16816(acc[mi][bj * 2 + 1], ah[mi], bl[bj][1], bl[bj][3]);
                }
#pragma unroll
            for (int mi = 0; mi < 2; mi++)
#pragma unroll
                for (int bj = 0; bj < 2; bj++) {
                    mma16816(acc[mi][bj * 2],     al[mi], bh[bj][0], bh[bj][2]);
                    mma16816(acc[mi][bj * 2 + 1], al[mi], bh[bj][1], bh[bj][3]);
                }
        }
        __syncthreads();
    }

    float* C = s2 ? C2 : C1;
    __half* Hh = s2 ? H2h : H1h;
    __half* Hl = s2 ? H2l : H1l;
#pragma unroll
    for (int mi = 0; mi < 2; mi++) {
        const int r = m0 + warp_m + mi * 16 + (lane >> 2);
#pragma unroll
        for (int j = 0; j < 4; j++) {
            const int col = n0 + warp_n + j * 8 + (lane & 3) * 2;
            float v00 = acc[mi][j][0], v01 = acc[mi][j][1];
            float v10 = acc[mi][j][2], v11 = acc[mi][j][3];
            if (mode == 0) {
                const float b0 = bias[col], b1 = bias[col + 1];
                *(float2*)(C + (size_t)r * N + col)       = make_float2(v00 + b0, v01 + b1);
                *(float2*)(C + (size_t)(r + 8) * N + col) = make_float2(v10 + b0, v11 + b1);
            } else {
                __half h00 = __float2half_rn(v00), h01 = __float2half_rn(v01);
                __half h10 = __float2half_rn(v10), h11 = __float2half_rn(v11);
                __half l00 = __float2half_rn(v00 - __half2float(h00));
                __half l01 = __float2half_rn(v01 - __half2float(h01));
                __half l10 = __float2half_rn(v10 - __half2float(h10));
                __half l11 = __float2half_rn(v11 - __half2float(h11));
                const size_t o0 = (size_t)r * N + col;
                const size_t o1 = (size_t)(r + 8) * N + col;
                *(ushort2*)(Hh + o0) = make_ushort2(__half_as_ushort(h00), __half_as_ushort(h01));
                *(ushort2*)(Hl + o0) = make_ushort2(__half_as_ushort(l00), __half_as_ushort(l01));
                *(ushort2*)(Hh + o1) = make_ushort2(__half_as_ushort(h10), __half_as_ushort(h11));
                *(ushort2*)(Hl + o1) = make_ushort2(__half_as_ushort(l10), __half_as_ushort(l11));
            }
        }
    }
}

// ================= HMMA flash attention: 2 CTAs/SM, merged branches ===========
#define ATT_QH 0
#define ATT_QL 16384
#define ATT_KV 32768
#define ATT_KV_STAGE 32768
#define ATT_SMEM 98304
#define ATT_KHo 0
#define ATT_KLo 8192
#define ATT_VHo 16384
#define ATT_VLo 24576

__global__ __launch_bounds__(256, 2)
void attn_hmma(const __half* __restrict__ Qh, const __half* __restrict__ Ql, int ldq,
               const __half* __restrict__ K1h, const __half* __restrict__ K1l,
               const __half* __restrict__ V1h, const __half* __restrict__ V1l, int ld1,
               const __half* __restrict__ K2h, const __half* __restrict__ K2l,
               const __half* __restrict__ V2h, const __half* __restrict__ V2l, int ld2,
               __nv_bfloat16* __restrict__ O1hi, __nv_bfloat16* __restrict__ O1lo,
               __nv_bfloat16* __restrict__ O2hi, __nv_bfloat16* __restrict__ O2lo)
{
    extern __shared__ __align__(1024) char smem[];
    const uint32_t sb = (uint32_t)__cvta_generic_to_shared(smem);
    const int t = threadIdx.x;
    const int lane = t & 31, wid = t >> 5;
    const int warp_m = wid * 16;
    const int bh = blockIdx.y;
    const int br = blockIdx.z;
    const int b = bh / 12, h = bh % 12;
    const int q0 = blockIdx.x * 128;
    const size_t rowbase = (size_t)b * 1024;

    const int ldkv = br ? ld2 : ld1;
    const __half* Kph = (br ? K2h : K1h) + rowbase * ldkv + h * 64;
    const __half* Kpl = (br ? K2l : K1l) + rowbase * ldkv + h * 64;
    const __half* Vph = (br ? V2h : V1h) + rowbase * ldkv + h * 64;
    const __half* Vpl = (br ? V2l : V1l) + rowbase * ldkv + h * 64;
    __nv_bfloat16* Ohi = br ? O2hi : O1hi;
    __nv_bfloat16* Olo = br ? O2lo : O1lo;
    const __half* Qph = Qh + (rowbase + q0) * ldq + h * 64;
    const __half* Qpl = Ql + (rowbase + q0) * ldq + h * 64;

    auto load_kv = [&](int c, int st) {
        const int k0 = c * 64;
        const uint32_t base = sb + ATT_KV + st * ATT_KV_STAGE;
#pragma unroll
        for (int i = 0; i < 8; i++) {
            const int idx = t + i * 256;
            const int sel = i >> 1;             // 0:KH 1:KL 2:VH 3:VL
            const int r = (idx >> 3) & 63, g = idx & 7;
            const __half* src = (sel == 0 ? Kph : sel == 1 ? Kpl
                                 : sel == 2 ? Vph : Vpl) + (size_t)(k0 + r) * ldkv + g * 8;
            const uint32_t off = base + sel * 8192 +
                                 (uint32_t)(r * 128 + ((g ^ (r & 7)) << 4));
            cp16(off, src);
        }
    };

#pragma unroll
    for (int i = 0; i < 8; i++) {
        const int idx = t + i * 256;
        const int sel = i >> 2;                 // 0:QH 1:QL
        const int r = (idx >> 3) & 127, g = idx & 7;
        const __half* src = (sel ? Qpl : Qph) + (size_t)r * ldq + g * 8;
        const uint32_t off = sb + (sel ? ATT_QL : ATT_QH) +
                             (uint32_t)(r * 128 + ((g ^ (r & 7)) << 4));
        cp16(off, src);
    }
    load_kv(0, 0);
    asm volatile("cp.async.commit_group;");

    float m_i[2], l_i[2], accO[8][4];
    m_i[0] = m_i[1] = -1e30f;
    l_i[0] = l_i[1] = 0.f;
#pragma unroll
    for (int f = 0; f < 8; f++)
#pragma unroll
        for (int v = 0; v < 4; v++) accO[f][v] = 0.f;

    const int f16  = lane & 15;
    const int gsel = lane >> 4;
    const int qrow = warp_m + f16;
    const uint32_t q_off = (uint32_t)(qrow * 128);
    const int qswz = qrow & 7;
    const int kswz = f16 & 7;
    const int vrow_l = (lane & 7) + 8 * ((lane >> 3) & 1);
    const int vswz = vrow_l & 7;

    for (int c = 0; c < 16; ++c) {
        const int st = c & 1;
        asm volatile("cp.async.wait_group 0;");
        __syncthreads();
        const uint32_t kvb = sb + ATT_KV + st * ATT_KV_STAGE;

        float sf[8][4];
#pragma unroll
        for (int f = 0; f < 8; f++)
#pragma unroll
            for (int v = 0; v < 4; v++) sf[f][v] = 0.f;

#pragma unroll
        for (int ks = 0; ks < 4; ks++) {
            const int kg = 2 * ks + gsel;
            uint32_t qh[4], ql[4];
            const uint32_t qa = sb + q_off + (uint32_t)((kg ^ qswz) << 4);
            ldsm4(qh, ATT_QH + qa);
            ldsm4(ql, ATT_QL + qa);

            uint32_t kh[4][4], kl[4][4];
#pragma unroll
            for (int np = 0; np < 4; np++) {
                const uint32_t ka = kvb + (uint32_t)((np * 16 + f16) * 128) +
                                    (uint32_t)((kg ^ kswz) << 4);
                ldsm4(kh[np], ATT_KHo + ka);
                ldsm4(kl[np], ATT_KLo + ka);
            }
#pragma unroll
            for (int np = 0; np < 4; np++) {
                mma_f16(sf[2 * np],     qh, kh[np][0], kh[np][2]);
                mma_f16(sf[2 * np + 1], qh, kh[np][1], kh[np][3]);
            }
#pragma unroll
            for (int np = 0; np < 4; np++) {
                mma_f16(sf[2 * np],     qh, kl[np][0], kl[np][2]);
                mma_f16(sf[2 * np + 1], qh, kl[np][1], kl[np][3]);
            }
#pragma unroll
            for (int np = 0; np < 4; np++) {
                mma_f16(sf[2 * np],     ql, kh[np][0], kh[np][2]);
                mma_f16(sf[2 * np + 1], ql, kh[np][1], kh[np][3]);
            }
        }

        if (c + 1 < 16) {
            load_kv(c + 1, st ^ 1);
            asm volatile("cp.async.commit_group;");
        }

        float mx0 = -1e30f, mx1 = -1e30f;
#pragma unroll
        for (int f = 0; f < 8; f++) {
            sf[f][0] *= 0.125f; sf[f][1] *= 0.125f;
            sf[f][2] *= 0.125f; sf[f][3] *= 0.125f;
            mx0 = fmaxf(mx0, fmaxf(sf[f][0], sf[f][1]));
            mx1 = fmaxf(mx1, fmaxf(sf[f][2], sf[f][3]));
        }
        mx0 = fmaxf(mx0, __shfl_xor_sync(0xffffffffu, mx0, 1));
        mx0 = fmaxf(mx0, __shfl_xor_sync(0xffffffffu, mx0, 2));
        mx1 = fmaxf(mx1, __shfl_xor_sync(0xffffffffu, mx1, 1));
        mx1 = fmaxf(mx1, __shfl_xor_sync(0xffffffffu, mx1, 2));

        const float mn0 = fmaxf(m_i[0], mx0);
        const float mn1 = fmaxf(m_i[1], mx1);
        const float al0 = __expf(m_i[0] - mn0);
        const float al1 = __expf(m_i[1] - mn1);
        m_i[0] = mn0; m_i[1] = mn1;

        float sum0 = 0.f, sum1 = 0.f;
#pragma unroll
        for (int f = 0; f < 8; f++) {
            sf[f][0] = __expf(sf[f][0] - mn0);
            sf[f][1] = __expf(sf[f][1] - mn0);
            sf[f][2] = __expf(sf[f][2] - mn1);
            sf[f][3] = __expf(sf[f][3] - mn1);
            sum0 += sf[f][0] + sf[f][1];
            sum1 += sf[f][2] + sf[f][3];
        }
        sum0 += __shfl_xor_sync(0xffffffffu, sum0, 1);
        sum0 += __shfl_xor_sync(0xffffffffu, sum0, 2);
        sum1 += __shfl_xor_sync(0xffffffffu, sum1, 1);
        sum1 += __shfl_xor_sync(0xffffffffu, sum1, 2);
        l_i[0] = l_i[0] * al0 + sum0;
        l_i[1] = l_i[1] * al1 + sum1;

#pragma unroll
        for (int f = 0; f < 8; f++) {
            accO[f][0] *= al0; accO[f][1] *= al0;
            accO[f][2] *= al1; accO[f][3] *= al1;
        }

#pragma unroll
        for (int ks = 0; ks < 4; ks++) {
            const int f0 = 2 * ks, f1 = 2 * ks + 1;
            uint32_t ah[4], alr[4];
            {
                __half2 a0 = __floats2half2_rn(sf[f0][0], sf[f0][1]);
                __half2 a1 = __floats2half2_rn(sf[f0][2], sf[f0][3]);
                __half2 a2 = __floats2half2_rn(sf[f1][0], sf[f1][1]);
                __half2 a3 = __floats2half2_rn(sf[f1][2], sf[f1][3]);
                float2 r0 = __half22float2(a0), r1 = __half22float2(a1);
                float2 r2 = __half22float2(a2), r3 = __half22float2(a3);
                ah[0] = h2u(a0); ah[1] = h2u(a1); ah[2] = h2u(a2); ah[3] = h2u(a3);
                alr[0] = h2u(__floats2half2_rn(sf[f0][0] - r0.x, sf[f0][1] - r0.y));
                alr[1] = h2u(__floats2half2_rn(sf[f0][2] - r1.x, sf[f0][3] - r1.y));
                alr[2] = h2u(__floats2half2_rn(sf[f1][0] - r2.x, sf[f1][1] - r2.y));
                alr[3] = h2u(__floats2half2_rn(sf[f1][2] - r3.x, sf[f1][3] - r3.y));
            }
            const int vrow = ks * 16 + vrow_l;
            uint32_t vh[4][4], vl[4][4];
#pragma unroll
            for (int g2 = 0; g2 < 4; g2++) {
                const int vg = 2 * g2 + gsel;
                const uint32_t va = kvb + (uint32_t)(vrow * 128) +
                                    (uint32_t)((vg ^ vswz) << 4);
                ldsm4t(vh[g2], ATT_VHo + va);
                ldsm4t(vl[g2], ATT_VLo + va);
            }
#pragma unroll
            for (int g2 = 0; g2 < 4; g2++) {
                mma_f16(accO[2 * g2],     ah, vh[g2][0], vh[g2][1]);
                mma_f16(accO[2 * g2 + 1], ah, vh[g2][2], vh[g2][3]);
            }
#pragma unroll
            for (int g2 = 0; g2 < 4; g2++) {
                mma_f16(accO[2 * g2],     ah, vl[g2][0], vl[g2][1]);
                mma_f16(accO[2 * g2 + 1], ah, vl[g2][2], vl[g2][3]);
            }
#pragma unroll
            for (int g2 = 0; g2 < 4; g2++) {
                mma_f16(accO[2 * g2],     alr, vh[g2][0], vh[g2][1]);
                mma_f16(accO[2 * g2 + 1], alr, vh[g2][2], vh[g2][3]);
            }
        }
    }

    const float inv0 = 1.f / l_i[0];
    const float inv1 = 1.f / l_i[1];
    const size_t r0 = rowbase + q0 + warp_m + (lane >> 2);
    const size_t r1 = r0 + 8;
    const int colb = h * 64 + (lane & 3) * 2;
#pragma unroll
    for (int f = 0; f < 8; f++) {
        float v00 = accO[f][0] * inv0, v01 = accO[f][1] * inv0;
        float v10 = accO[f][2] * inv1, v11 = accO[f][3] * inv1;
        __nv_bfloat16 h00 = __float2bfloat16_rn(v00);
        __nv_bfloat16 h01 = __float2bfloat16_rn(v01);
        __nv_bfloat16 h10 = __float2bfloat16_rn(v10);
        __nv_bfloat16 h11 = __float2bfloat16_rn(v11);
        __nv_bfloat16 l00 = __float2bfloat16_rn(v00 - __bfloat162float(h00));
        __nv_bfloat16 l01 = __float2bfloat16_rn(v01 - __bfloat162float(h01));
        __nv_bfloat16 l10 = __float2bfloat16_rn(v10 - __bfloat162float(h10));
        __nv_bfloat16 l11 = __float2bfloat16_rn(v11 - __bfloat162float(h11));
        const size_t o0 = r0 * 768 + colb + 8 * f;
        const size_t o1 = r1 * 768 + colb + 8 * f;
        *(ushort2*)(Ohi + o0) = make_ushort2(__bfloat16_as_ushort(h00), __bfloat16_as_ushort(h01));
        *(ushort2*)(Olo + o0) = make_ushort2(__bfloat16_as_ushort(l00), __bfloat16_as_ushort(l01));
        *(ushort2*)(Ohi + o1) = make_ushort2(__bfloat16_as_ushort(h10), __bfloat16_as_ushort(h11));
        *(ushort2*)(Olo + o1) = make_ushort2(__bfloat16_as_ushort(l10), __bfloat16_as_ushort(l11));
    }
}

// ================= launch =================
extern "C" void kernel_launch(void* const* d_in, const int* in_sizes, int n_in,
                              void* d_out, int out_size)
{
    const float* x      = (const float*)d_in[0];
    const float* x2     = (const float*)d_in[1];
    const float* qkv_w  = (const float*)d_in[2];
    const float* proj_w = (const float*)d_in[3];
    const float* proj_b = (const float*)d_in[4];
    float* out = (float*)d_out;

    __half *qkvh, *qkvl, *kv2h, *kv2l;
    __nv_bfloat16 *xhi, *xlo, *x2hi, *x2lo, *wqhi, *wqlo, *wphi, *wplo;
    __nv_bfloat16 *o1hi, *o1lo, *o2hi, *o2lo;
    cudaGetSymbolAddress((void**)&qkvh, g_qkvh);
    cudaGetSymbolAddress((void**)&qkvl, g_qkvl);
    cudaGetSymbolAddress((void**)&kv2h, g_kv2h);
    cudaGetSymbolAddress((void**)&kv2l, g_kv2l);
    cudaGetSymbolAddress((void**)&xhi,  g_xhi);
    cudaGetSymbolAddress((void**)&xlo,  g_xlo);
    cudaGetSymbolAddress((void**)&x2hi, g_x2hi);
    cudaGetSymbolAddress((void**)&x2lo, g_x2lo);
    cudaGetSymbolAddress((void**)&wqhi, g_wqhi);
    cudaGetSymbolAddress((void**)&wqlo, g_wqlo);
    cudaGetSymbolAddress((void**)&wphi, g_wphi);
    cudaGetSymbolAddress((void**)&wplo, g_wplo);
    cudaGetSymbolAddress((void**)&o1hi, g_o1hi);
    cudaGetSymbolAddress((void**)&o1lo, g_o1lo);
    cudaGetSymbolAddress((void**)&o2hi, g_o2hi);
    cudaGetSymbolAddress((void**)&o2lo, g_o2lo);

    cudaFuncSetAttribute(gemm_hmma, cudaFuncAttributeMaxDynamicSharedMemorySize, GEMM_SMEM);
    cudaFuncSetAttribute(attn_hmma, cudaFuncAttributeMaxDynamicSharedMemorySize, ATT_SMEM);

    const int M = 8192;

    {
        int n4 = 8192 * 768 / 4;
        split_bf16<<<n4 / 256, 256>>>((const float4*)x,  (uint2*)xhi,  (uint2*)xlo,  n4);
        split_bf16<<<n4 / 256, 256>>>((const float4*)x2, (uint2*)x2hi, (uint2*)x2lo, n4);
    }
    {
        int n4 = 2304 * 768 / 4;
        split_bf16<<<n4 / 256, 256>>>((const float4*)qkv_w, (uint2*)wqhi, (uint2*)wqlo, n4);
    }
    {
        int n4 = 768 * 768 / 4;
        split_bf16<<<n4 / 256, 256>>>((const float4*)proj_w, (uint2*)wphi, (uint2*)wplo, n4);
    }

    // QKV (x, 18 n-tiles) + KV2 (x2, 12 n-tiles) in one launch; fp16 hi/lo out
    gemm_hmma<<<dim3(30, M / 128), 512, GEMM_SMEM>>>(
        xhi, xlo, x2hi, x2lo, wqhi, wqlo,
        nullptr, nullptr, nullptr,
        qkvh, qkvl, kv2h, kv2l,
        18, 2304, 1536, 768, 1);

    // both attention branches in one launch (z = branch)
    attn_hmma<<<dim3(8, 96, 2), 256, ATT_SMEM>>>(
        qkvh, qkvl, 2304,
        qkvh + 768, qkvl + 768, qkvh + 1536, qkvl + 1536, 2304,
        kv2h, kv2l, kv2h + 768, kv2l + 768, 1536,
        o1hi, o1lo, o2hi, o2lo);

    // both output projections (+bias) in one launch (6 + 6 n-tiles)
    gemm_hmma<<<dim3(12, M / 128), 512, GEMM_SMEM>>>(
        o1hi, o1lo, o2hi, o2lo, wphi, wplo,
        out, out + (size_t)M * 768, proj_b,
        nullptr, nullptr, nullptr, nullptr,
        6, 768, 768, 0, 0);
}

// round 14
// speedup vs baseline: 1.1606x; 1.1606x over previous
#include <cuda_runtime.h>
#include <cuda_bf16.h>
#include <cuda_fp16.h>
#include <cstdint>

// ================= scratch (no allocations allowed) =================
__device__ __align__(256) __half g_qkvh[8192 * 2304], g_qkvl[8192 * 2304]; // q|k|v fp16 hi/lo
__device__ __align__(256) __half g_kv2h[8192 * 1536], g_kv2l[8192 * 1536]; // k2|v2 fp16 hi/lo

__device__ __align__(256) __nv_bfloat16 g_xhi[8192 * 768],  g_xlo[8192 * 768];
__device__ __align__(256) __nv_bfloat16 g_x2hi[8192 * 768], g_x2lo[8192 * 768];
__device__ __align__(256) __nv_bfloat16 g_wqhi[2304 * 768], g_wqlo[2304 * 768];
__device__ __align__(256) __nv_bfloat16 g_wphi[768 * 768],  g_wplo[768 * 768];
__device__ __align__(256) __nv_bfloat16 g_o1hi[8192 * 768], g_o1lo[8192 * 768];
__device__ __align__(256) __nv_bfloat16 g_o2hi[8192 * 768], g_o2lo[8192 * 768];

// ================= helpers =================
__device__ __forceinline__ void cp16(uint32_t s, const void* g) {
    asm volatile("cp.async.cg.shared.global [%0], [%1], 16;" :: "r"(s), "l"(g));
}

__device__ __forceinline__ void ldsm4(uint32_t* r, uint32_t addr) {
    asm volatile("ldmatrix.sync.aligned.m8n8.x4.shared.b16 {%0,%1,%2,%3}, [%4];"
                 : "=r"(r[0]), "=r"(r[1]), "=r"(r[2]), "=r"(r[3]) : "r"(addr));
}

__device__ __forceinline__ void ldsm4t(uint32_t* r, uint32_t addr) {
    asm volatile("ldmatrix.sync.aligned.m8n8.x4.trans.shared.b16 {%0,%1,%2,%3}, [%4];"
                 : "=r"(r[0]), "=r"(r[1]), "=r"(r[2]), "=r"(r[3]) : "r"(addr));
}

__device__ __forceinline__ void mma16816(float* c, const uint32_t* a,
                                         uint32_t b0, uint32_t b1) {
    asm volatile(
        "mma.sync.aligned.m16n8k16.row.col.f32.bf16.bf16.f32 "
        "{%0,%1,%2,%3}, {%4,%5,%6,%7}, {%8,%9}, {%0,%1,%2,%3};"
        : "+f"(c[0]), "+f"(c[1]), "+f"(c[2]), "+f"(c[3])
        : "r"(a[0]), "r"(a[1]), "r"(a[2]), "r"(a[3]), "r"(b0), "r"(b1));
}

__device__ __forceinline__ void mma_f16(float* c, const uint32_t* a,
                                        uint32_t b0, uint32_t b1) {
    asm volatile(
        "mma.sync.aligned.m16n8k16.row.col.f32.f16.f16.f32 "
        "{%0,%1,%2,%3}, {%4,%5,%6,%7}, {%8,%9}, {%0,%1,%2,%3};"
        : "+f"(c[0]), "+f"(c[1]), "+f"(c[2]), "+f"(c[3])
        : "r"(a[0]), "r"(a[1]), "r"(a[2]), "r"(a[3]), "r"(b0), "r"(b1));
}

__device__ __forceinline__ uint32_t h2u(__half2 h) { return *(uint32_t*)&h; }

// ================= bf16 hi/lo split =================
__global__ __launch_bounds__(256)
void split_bf16(const float4* __restrict__ src, uint2* __restrict__ hi,
                uint2* __restrict__ lo, int n4)
{
    int i = blockIdx.x * blockDim.x + threadIdx.x;
    if (i >= n4) return;
    float4 v = src[i];
    float f[4] = {v.x, v.y, v.z, v.w};
    uint32_t h[4], l[4];
#pragma unroll
    for (int j = 0; j < 4; j++) {
        __nv_bfloat16 hb = __float2bfloat16_rn(f[j]);
        float r = f[j] - __bfloat162float(hb);
        __nv_bfloat16 lb = __float2bfloat16_rn(r);
        h[j] = (uint32_t)__bfloat16_as_ushort(hb);
        l[j] = (uint32_t)__bfloat16_as_ushort(lb);
    }
    hi[i] = make_uint2(h[0] | (h[1] << 16), h[2] | (h[3] << 16));
    lo[i] = make_uint2(l[0] | (l[1] << 16), l[2] | (l[3] << 16));
}

// ========= HMMA bf16x3 GEMM: 128x64 tile, 2 CTAs/SM, dual A-stream ==========
// bx < nx1 -> stream 1, else stream 2 (n-tile index resets).
#define GT_AH 0
#define GT_AL 16384
#define GT_BH 32768
#define GT_BL 40960
#define G_STAGE 49152
#define GEMM_SMEM (2 * G_STAGE)

__global__ __launch_bounds__(256, 2)
void gemm_hmma(const __nv_bfloat16* __restrict__ A1hi, const __nv_bfloat16* __restrict__ A1lo,
               const __nv_bfloat16* __restrict__ A2hi, const __nv_bfloat16* __restrict__ A2lo,
               const __nv_bfloat16* __restrict__ Bhi, const __nv_bfloat16* __restrict__ Blo,
               float* __restrict__ C1, float* __restrict__ C2, const float* __restrict__ bias,
               __half* __restrict__ H1h, __half* __restrict__ H1l,
               __half* __restrict__ H2h, __half* __restrict__ H2l,
               int nx1, int N1, int N2, int woff2, int mode)
{
    extern __shared__ __align__(1024) char smem[];
    const uint32_t sb = (uint32_t)__cvta_generic_to_shared(smem);
    const int t = threadIdx.x;
    const int wid = t >> 5, lane = t & 31;
    const int m0 = blockIdx.y * 128;
    const int K = 768, NC = 12;

    const int s2 = (int)blockIdx.x >= nx1;
    const int bx = s2 ? (int)blockIdx.x - nx1 : (int)blockIdx.x;
    const int n0 = bx * 64;
    const int N = s2 ? N2 : N1;
    const int woff = s2 ? woff2 : 0;

    const int warp_m = (wid >> 1) * 32;
    const int warp_n = (wid & 1) * 32;

    float acc[2][4][4];
#pragma unroll
    for (int i = 0; i < 2; i++)
#pragma unroll
        for (int j = 0; j < 4; j++)
#pragma unroll
            for (int v = 0; v < 4; v++) acc[i][j][v] = 0.f;

    const __nv_bfloat16* Ah = (s2 ? A2hi : A1hi) + (size_t)m0 * K;
    const __nv_bfloat16* Al = (s2 ? A2lo : A1lo) + (size_t)m0 * K;
    const __nv_bfloat16* Bh = Bhi + (size_t)(woff + n0) * K;
    const __nv_bfloat16* Bl = Blo + (size_t)(woff + n0) * K;

    auto load_chunk = [&](int c, int st) {
        const int kc = c * 64;
        const uint32_t base = sb + st * G_STAGE;
#pragma unroll
        for (int i = 0; i < 4; i++) {            // A: 1024 granules, 4/thread
            const int gi = t + i * 256;
            const int row = gi >> 3, g = gi & 7;
            const uint32_t loff = (uint32_t)(row * 128 + ((g ^ (row & 7)) << 4));
            const size_t goff = (size_t)row * K + kc + g * 8;
            cp16(base + GT_AH + loff, Ah + goff);
            cp16(base + GT_AL + loff, Al + goff);
        }
#pragma unroll
        for (int i = 0; i < 2; i++) {            // B: 512 granules, 2/thread
            const int gi = t + i * 256;
            const int row = gi >> 3, g = gi & 7;
            const uint32_t loff = (uint32_t)(row * 128 + ((g ^ (row & 7)) << 4));
            const size_t goff = (size_t)row * K + kc + g * 8;
            cp16(base + GT_BH + loff, Bh + goff);
            cp16(base + GT_BL + loff, Bl + goff);
        }
        asm volatile("cp.async.commit_group;");
    };

    const int fr   = lane & 15;
    const int half = lane >> 4;
    const int arow = warp_m + fr;
    const int brow = warp_n + fr;
    const int aswz = arow & 7;
    const int bswz = brow & 7;
    const uint32_t arow_off = (uint32_t)(arow * 128);
    const uint32_t brow_off = (uint32_t)(brow * 128);

    load_chunk(0, 0);

    for (int c = 0; c < NC; ++c) {
        const int st = c & 1;
        if (c + 1 < NC) {
            load_chunk(c + 1, st ^ 1);
            asm volatile("cp.async.wait_group 1;");
        } else {
            asm volatile("cp.async.wait_group 0;");
        }
        __syncthreads();

        const uint32_t base = sb + st * G_STAGE;
#pragma unroll
        for (int kk = 0; kk < 4; kk++) {
            const int kg = kk * 2 + half;
            const uint32_t aoff = arow_off + (uint32_t)((kg ^ aswz) << 4);
            const uint32_t boff = brow_off + (uint32_t)((kg ^ bswz) << 4);

            uint32_t ah[2][4], al[2][4], bh[2][4], bl[2][4];
#pragma unroll
            for (int mi = 0; mi < 2; mi++) {
                ldsm4(ah[mi], base + GT_AH + aoff + mi * (16 * 128));
                ldsm4(al[mi], base + GT_AL + aoff + mi * (16 * 128));
            }
#pragma unroll
            for (int bj = 0; bj < 2; bj++) {
                ldsm4(bh[bj], base + GT_BH + boff + bj * (16 * 128));
                ldsm4(bl[bj], base + GT_BL + boff + bj * (16 * 128));
            }
#pragma unroll
            for (int mi = 0; mi < 2; mi++)
#pragma unroll
                for (int bj = 0; bj < 2; bj++) {
                    mma16816(acc[mi][bj * 2],     ah[mi], bh[bj][0], bh[bj][2]);
                    mma16816(acc[mi][bj * 2 + 1], ah[mi], bh[bj][1], bh[bj][3]);
                }
#pragma unroll
            for (int mi = 0; mi < 2; mi++)
#pragma unroll
                for (int bj = 0; bj < 2; bj++) {
                    mma16816(acc[mi][bj * 2],     ah[mi], bl[bj][0], bl[bj][2]);
                    mma16816(acc[mi][bj * 2 + 1], ah[mi], bl[bj][1], bl[bj][3]);
                }
#pragma unroll
            for (int mi = 0; mi < 2; mi++)
#pragma unroll
                for (int bj = 0; bj < 2; bj++) {
                    mma16816(acc[mi][bj * 2],     al[mi], bh[bj][0], bh[bj][2]);
                    mma16816(acc[mi][bj * 2 + 1], al[mi], bh[bj][1], bh[bj][3]);
                }
        }
        __syncthreads();
    }

    float* C = s2 ? C2 : C1;
    __half* Hh = s2 ? H2h : H1h;
    __half* Hl = s2 ? H2l : H1l;
#pragma unroll
    for (int mi = 0; mi < 2; mi++) {
        const int r = m0 + warp_m + mi * 16 + (lane >> 2);
#pragma unroll
        for (int j = 0; j < 4; j++) {
            const int col = n0 + warp_n + j * 8 + (lane & 3) * 2;
            float v00 = acc[mi][j][0], v01 = acc[mi][j][1];
            float v10 = acc[mi][j][2], v11 = acc[mi][j][3];
            if (mode == 0) {
                const float b0 = bias[col], b1 = bias[col + 1];
                *(float2*)(C + (size_t)r * N + col)       = make_float2(v00 + b0, v01 + b1);
                *(float2*)(C + (size_t)(r + 8) * N + col) = make_float2(v10 + b0, v11 + b1);
            } else {
                __half h00 = __float2half_rn(v00), h01 = __float2half_rn(v01);
                __half h10 = __float2half_rn(v10), h11 = __float2half_rn(v11);
                __half l00 = __float2half_rn(v00 - __half2float(h00));
                __half l01 = __float2half_rn(v01 - __half2float(h01));
                __half l10 = __float2half_rn(v10 - __half2float(h10));
                __half l11 = __float2half_rn(v11 - __half2float(h11));
                const size_t o0 = (size_t)r * N + col;
                const size_t o1 = (size_t)(r + 8) * N + col;
                *(ushort2*)(Hh + o0) = make_ushort2(__half_as_ushort(h00), __half_as_ushort(h01));
                *(ushort2*)(Hl + o0) = make_ushort2(__half_as_ushort(l00), __half_as_ushort(l01));
                *(ushort2*)(Hh + o1) = make_ushort2(__half_as_ushort(h10), __half_as_ushort(h11));
                *(ushort2*)(Hl + o1) = make_ushort2(__half_as_ushort(l10), __half_as_ushort(l11));
            }
        }
    }
}

// ======= HMMA flash attention: 2 CTAs/SM, merged branches, PV 2-term =========
#define ATT_QH 0
#define ATT_QL 16384
#define ATT_KV 32768
#define ATT_KV_STAGE 32768
#define ATT_SMEM 98304
#define ATT_KHo 0
#define ATT_KLo 8192
#define ATT_VHo 16384
#define ATT_VLo 24576

__global__ __launch_bounds__(256, 2)
void attn_hmma(const __half* __restrict__ Qh, const __half* __restrict__ Ql, int ldq,
               const __half* __restrict__ K1h, const __half* __restrict__ K1l,
               const __half* __restrict__ V1h, const __half* __restrict__ V1l, int ld1,
               const __half* __restrict__ K2h, const __half* __restrict__ K2l,
               const __half* __restrict__ V2h, const __half* __restrict__ V2l, int ld2,
               __nv_bfloat16* __restrict__ O1hi, __nv_bfloat16* __restrict__ O1lo,
               __nv_bfloat16* __restrict__ O2hi, __nv_bfloat16* __restrict__ O2lo)
{
    extern __shared__ __align__(1024) char smem[];
    const uint32_t sb = (uint32_t)__cvta_generic_to_shared(smem);
    const int t = threadIdx.x;
    const int lane = t & 31, wid = t >> 5;
    const int warp_m = wid * 16;
    const int bh = blockIdx.y;
    const int br = blockIdx.z;
    const int b = bh / 12, h = bh % 12;
    const int q0 = blockIdx.x * 128;
    const size_t rowbase = (size_t)b * 1024;

    const int ldkv = br ? ld2 : ld1;
    const __half* Kph = (br ? K2h : K1h) + rowbase * ldkv + h * 64;
    const __half* Kpl = (br ? K2l : K1l) + rowbase * ldkv + h * 64;
    const __half* Vph = (br ? V2h : V1h) + rowbase * ldkv + h * 64;
    const __half* Vpl = (br ? V2l : V1l) + rowbase * ldkv + h * 64;
    __nv_bfloat16* Ohi = br ? O2hi : O1hi;
    __nv_bfloat16* Olo = br ? O2lo : O1lo;
    const __half* Qph = Qh + (rowbase + q0) * ldq + h * 64;
    const __half* Qpl = Ql + (rowbase + q0) * ldq + h * 64;

    auto load_kv = [&](int c, int st) {
        const int k0 = c * 64;
        const uint32_t base = sb + ATT_KV + st * ATT_KV_STAGE;
#pragma unroll
        for (int i = 0; i < 8; i++) {
            const int idx = t + i * 256;
            const int sel = i >> 1;             // 0:KH 1:KL 2:VH 3:VL
            const int r = (idx >> 3) & 63, g = idx & 7;
            const __half* src = (sel == 0 ? Kph : sel == 1 ? Kpl
                                 : sel == 2 ? Vph : Vpl) + (size_t)(k0 + r) * ldkv + g * 8;
            const uint32_t off = base + sel * 8192 +
                                 (uint32_t)(r * 128 + ((g ^ (r & 7)) << 4));
            cp16(off, src);
        }
    };

#pragma unroll
    for (int i = 0; i < 8; i++) {
        const int idx = t + i * 256;
        const int sel = i >> 2;                 // 0:QH 1:QL
        const int r = (idx >> 3) & 127, g = idx & 7;
        const __half* src = (sel ? Qpl : Qph) + (size_t)r * ldq + g * 8;
        const uint32_t off = sb + (sel ? ATT_QL : ATT_QH) +
                             (uint32_t)(r * 128 + ((g ^ (r & 7)) << 4));
        cp16(off, src);
    }
    load_kv(0, 0);
    asm volatile("cp.async.commit_group;");

    float m_i[2], l_i[2], accO[8][4];
    m_i[0] = m_i[1] = -1e30f;
    l_i[0] = l_i[1] = 0.f;
#pragma unroll
    for (int f = 0; f < 8; f++)
#pragma unroll
        for (int v = 0; v < 4; v++) accO[f][v] = 0.f;

    const int f16  = lane & 15;
    const int gsel = lane >> 4;
    const int qrow = warp_m + f16;
    const uint32_t q_off = (uint32_t)(qrow * 128);
    const int qswz = qrow & 7;
    const int kswz = f16 & 7;
    const int vrow_l = (lane & 7) + 8 * ((lane >> 3) & 1);
    const int vswz = vrow_l & 7;

    for (int c = 0; c < 16; ++c) {
        const int st = c & 1;
        asm volatile("cp.async.wait_group 0;");
        __syncthreads();
        const uint32_t kvb = sb + ATT_KV + st * ATT_KV_STAGE;

        float sf[8][4];
#pragma unroll
        for (int f = 0; f < 8; f++)
#pragma unroll
            for (int v = 0; v < 4; v++) sf[f][v] = 0.f;

#pragma unroll
        for (int ks = 0; ks < 4; ks++) {
            const int kg = 2 * ks + gsel;
            uint32_t qh[4], ql[4];
            const uint32_t qa = sb + q_off + (uint32_t)((kg ^ qswz) << 4);
            ldsm4(qh, ATT_QH + qa);
            ldsm4(ql, ATT_QL + qa);

            uint32_t kh[4][4], kl[4][4];
#pragma unroll
            for (int np = 0; np < 4; np++) {
                const uint32_t ka = kvb + (uint32_t)((np * 16 + f16) * 128) +
                                    (uint32_t)((kg ^ kswz) << 4);
                ldsm4(kh[np], ATT_KHo + ka);
                ldsm4(kl[np], ATT_KLo + ka);
            }
#pragma unroll
            for (int np = 0; np < 4; np++) {
                mma_f16(sf[2 * np],     qh, kh[np][0], kh[np][2]);
                mma_f16(sf[2 * np + 1], qh, kh[np][1], kh[np][3]);
            }
#pragma unroll
            for (int np = 0; np < 4; np++) {
                mma_f16(sf[2 * np],     qh, kl[np][0], kl[np][2]);
                mma_f16(sf[2 * np + 1], qh, kl[np][1], kl[np][3]);
            }
#pragma unroll
            for (int np = 0; np < 4; np++) {
                mma_f16(sf[2 * np],     ql, kh[np][0], kh[np][2]);
                mma_f16(sf[2 * np + 1], ql, kh[np][1], kh[np][3]);
            }
        }

        if (c + 1 < 16) {
            load_kv(c + 1, st ^ 1);
            asm volatile("cp.async.commit_group;");
        }

        float mx0 = -1e30f, mx1 = -1e30f;
#pragma unroll
        for (int f = 0; f < 8; f++) {
            sf[f][0] *= 0.125f; sf[f][1] *= 0.125f;
            sf[f][2] *= 0.125f; sf[f][3] *= 0.125f;
            mx0 = fmaxf(mx0, fmaxf(sf[f][0], sf[f][1]));
            mx1 = fmaxf(mx1, fmaxf(sf[f][2], sf[f][3]));
        }
        mx0 = fmaxf(mx0, __shfl_xor_sync(0xffffffffu, mx0, 1));
        mx0 = fmaxf(mx0, __shfl_xor_sync(0xffffffffu, mx0, 2));
        mx1 = fmaxf(mx1, __shfl_xor_sync(0xffffffffu, mx1, 1));
        mx1 = fmaxf(mx1, __shfl_xor_sync(0xffffffffu, mx1, 2));

        const float mn0 = fmaxf(m_i[0], mx0);
        const float mn1 = fmaxf(m_i[1], mx1);
        const float al0 = __expf(m_i[0] - mn0);
        const float al1 = __expf(m_i[1] - mn1);
        m_i[0] = mn0; m_i[1] = mn1;

        float sum0 = 0.f, sum1 = 0.f;
#pragma unroll
        for (int f = 0; f < 8; f++) {
            sf[f][0] = __expf(sf[f][0] - mn0);
            sf[f][1] = __expf(sf[f][1] - mn0);
            sf[f][2] = __expf(sf[f][2] - mn1);
            sf[f][3] = __expf(sf[f][3] - mn1);
            sum0 += sf[f][0] + sf[f][1];
            sum1 += sf[f][2] + sf[f][3];
        }
        sum0 += __shfl_xor_sync(0xffffffffu, sum0, 1);
        sum0 += __shfl_xor_sync(0xffffffffu, sum0, 2);
        sum1 += __shfl_xor_sync(0xffffffffu, sum1, 1);
        sum1 += __shfl_xor_sync(0xffffffffu, sum1, 2);
        l_i[0] = l_i[0] * al0 + sum0;
        l_i[1] = l_i[1] * al1 + sum1;

#pragma unroll
        for (int f = 0; f < 8; f++) {
            accO[f][0] *= al0; accO[f][1] *= al0;
            accO[f][2] *= al1; accO[f][3] *= al1;
        }

        // ---- O += P V (2-term: ph*vh + ph*vl; pl term dropped, ~2^-12 rel) ----
#pragma unroll
        for (int ks = 0; ks < 4; ks++) {
            const int f0 = 2 * ks, f1 = 2 * ks + 1;
            uint32_t ah[4];
            ah[0] = h2u(__floats2half2_rn(sf[f0][0], sf[f0][1]));
            ah[1] = h2u(__floats2half2_rn(sf[f0][2], sf[f0][3]));
            ah[2] = h2u(__floats2half2_rn(sf[f1][0], sf[f1][1]));
            ah[3] = h2u(__floats2half2_rn(sf[f1][2], sf[f1][3]));

            const int vrow = ks * 16 + vrow_l;
            uint32_t vh[4][4], vl[4][4];
#pragma unroll
            for (int g2 = 0; g2 < 4; g2++) {
                const int vg = 2 * g2 + gsel;
                const uint32_t va = kvb + (uint32_t)(vrow * 128) +
                                    (uint32_t)((vg ^ vswz) << 4);
                ldsm4t(vh[g2], ATT_VHo + va);
                ldsm4t(vl[g2], ATT_VLo + va);
            }
#pragma unroll
            for (int g2 = 0; g2 < 4; g2++) {
                mma_f16(accO[2 * g2],     ah, vh[g2][0], vh[g2][1]);
                mma_f16(accO[2 * g2 + 1], ah, vh[g2][2], vh[g2][3]);
            }
#pragma unroll
            for (int g2 = 0; g2 < 4; g2++) {
                mma_f16(accO[2 * g2],     ah, vl[g2][0], vl[g2][1]);
                mma_f16(accO[2 * g2 + 1], ah, vl[g2][2], vl[g2][3]);
            }
        }
    }

    const float inv0 = 1.f / l_i[0];
    const float inv1 = 1.f / l_i[1];
    const size_t r0 = rowbase + q0 + warp_m + (lane >> 2);
    const size_t r1 = r0 + 8;
    const int colb = h * 64 + (lane & 3) * 2;
#pragma unroll
    for (int f = 0; f < 8; f++) {
        float v00 = accO[f][0] * inv0, v01 = accO[f][1] * inv0;
        float v10 = accO[f][2] * inv1, v11 = accO[f][3] * inv1;
        __nv_bfloat16 h00 = __float2bfloat16_rn(v00);
        __nv_bfloat16 h01 = __float2bfloat16_rn(v01);
        __nv_bfloat16 h10 = __float2bfloat16_rn(v10);
        __nv_bfloat16 h11 = __float2bfloat16_rn(v11);
        __nv_bfloat16 l00 = __float2bfloat16_rn(v00 - __bfloat162float(h00));
        __nv_bfloat16 l01 = __float2bfloat16_rn(v01 - __bfloat162float(h01));
        __nv_bfloat16 l10 = __float2bfloat16_rn(v10 - __bfloat162float(h10));
        __nv_bfloat16 l11 = __float2bfloat16_rn(v11 - __bfloat162float(h11));
        const size_t o0 = r0 * 768 + colb + 8 * f;
        const size_t o1 = r1 * 768 + colb + 8 * f;
        *(ushort2*)(Ohi + o0) = make_ushort2(__bfloat16_as_ushort(h00), __bfloat16_as_ushort(h01));
        *(ushort2*)(Olo + o0) = make_ushort2(__bfloat16_as_ushort(l00), __bfloat16_as_ushort(l01));
        *(ushort2*)(Ohi + o1) = make_ushort2(__bfloat16_as_ushort(h10), __bfloat16_as_ushort(h11));
        *(ushort2*)(Olo + o1) = make_ushort2(__bfloat16_as_ushort(l10), __bfloat16_as_ushort(l11));
    }
}

// ================= launch =================
extern "C" void kernel_launch(void* const* d_in, const int* in_sizes, int n_in,
                              void* d_out, int out_size)
{
    const float* x      = (const float*)d_in[0];
    const float* x2     = (const float*)d_in[1];
    const float* qkv_w  = (const float*)d_in[2];
    const float* proj_w = (const float*)d_in[3];
    const float* proj_b = (const float*)d_in[4];
    float* out = (float*)d_out;

    __half *qkvh, *qkvl, *kv2h, *kv2l;
    __nv_bfloat16 *xhi, *xlo, *x2hi, *x2lo, *wqhi, *wqlo, *wphi, *wplo;
    __nv_bfloat16 *o1hi, *o1lo, *o2hi, *o2lo;
    cudaGetSymbolAddress((void**)&qkvh, g_qkvh);
    cudaGetSymbolAddress((void**)&qkvl, g_qkvl);
    cudaGetSymbolAddress((void**)&kv2h, g_kv2h);
    cudaGetSymbolAddress((void**)&kv2l, g_kv2l);
    cudaGetSymbolAddress((void**)&xhi,  g_xhi);
    cudaGetSymbolAddress((void**)&xlo,  g_xlo);
    cudaGetSymbolAddress((void**)&x2hi, g_x2hi);
    cudaGetSymbolAddress((void**)&x2lo, g_x2lo);
    cudaGetSymbolAddress((void**)&wqhi, g_wqhi);
    cudaGetSymbolAddress((void**)&wqlo, g_wqlo);
    cudaGetSymbolAddress((void**)&wphi, g_wphi);
    cudaGetSymbolAddress((void**)&wplo, g_wplo);
    cudaGetSymbolAddress((void**)&o1hi, g_o1hi);
    cudaGetSymbolAddress((void**)&o1lo, g_o1lo);
    cudaGetSymbolAddress((void**)&o2hi, g_o2hi);
    cudaGetSymbolAddress((void**)&o2lo, g_o2lo);

    cudaFuncSetAttribute(gemm_hmma, cudaFuncAttributeMaxDynamicSharedMemorySize, GEMM_SMEM);
    cudaFuncSetAttribute(attn_hmma, cudaFuncAttributeMaxDynamicSharedMemorySize, ATT_SMEM);

    const int M = 8192;

    {
        int n4 = 8192 * 768 / 4;
        split_bf16<<<n4 / 256, 256>>>((const float4*)x,  (uint2*)xhi,  (uint2*)xlo,  n4);
        split_bf16<<<n4 / 256, 256>>>((const float4*)x2, (uint2*)x2hi, (uint2*)x2lo, n4);
    }
    {
        int n4 = 2304 * 768 / 4;
        split_bf16<<<n4 / 256, 256>>>((const float4*)qkv_w, (uint2*)wqhi, (uint2*)wqlo, n4);
    }
    {
        int n4 = 768 * 768 / 4;
        split_bf16<<<n4 / 256, 256>>>((const float4*)proj_w, (uint2*)wphi, (uint2*)wplo, n4);
    }

    // QKV (x, 36 n-tiles) + KV2 (x2, 24 n-tiles) in one launch; fp16 hi/lo out
    gemm_hmma<<<dim3(60, M / 128), 256, GEMM_SMEM>>>(
        xhi, xlo, x2hi, x2lo, wqhi, wqlo,
        nullptr, nullptr, nullptr,
        qkvh, qkvl, kv2h, kv2l,
        36, 2304, 1536, 768, 1);

    // both attention branches in one launch (z = branch)
    attn_hmma<<<dim3(8, 96, 2), 256, ATT_SMEM>>>(
        qkvh, qkvl, 2304,
        qkvh + 768, qkvl + 768, qkvh + 1536, qkvl + 1536, 2304,
        kv2h, kv2l, kv2h + 768, kv2l + 768, 1536,
        o1hi, o1lo, o2hi, o2lo);

    // both output projections (+bias) in one launch (12 + 12 n-tiles)
    gemm_hmma<<<dim3(24, M / 128), 256, GEMM_SMEM>>>(
        o1hi, o1lo, o2hi, o2lo, wphi, wplo,
        out, out + (size_t)M * 768, proj_b,
        nullptr, nullptr, nullptr, nullptr,
        12, 768, 768, 0, 0);
}

// round 15
// speedup vs baseline: 1.2557x; 1.0819x over previous
#include <cuda_runtime.h>
#include <cuda_fp16.h>
#include <cstdint>

// ================= scratch (no allocations allowed) =================
__device__ __align__(256) __half g_qkvh[8192 * 2304], g_qkvl[8192 * 2304]; // q|k|v fp16 hi/lo
__device__ __align__(256) __half g_kv2h[8192 * 1536], g_kv2l[8192 * 1536]; // k2|v2 fp16 hi/lo

__device__ __align__(256) __half g_xhi[8192 * 768],  g_xlo[8192 * 768];
__device__ __align__(256) __half g_x2hi[8192 * 768], g_x2lo[8192 * 768];
__device__ __align__(256) __half g_wqhi[2304 * 768], g_wqlo[2304 * 768];
__device__ __align__(256) __half g_wphi[768 * 768],  g_wplo[768 * 768];
__device__ __align__(256) __half g_o1hi[8192 * 768], g_o1lo[8192 * 768];
__device__ __align__(256) __half g_o2hi[8192 * 768], g_o2lo[8192 * 768];

// ================= helpers =================
__device__ __forceinline__ void cp16(uint32_t s, const void* g) {
    asm volatile("cp.async.cg.shared.global [%0], [%1], 16;" :: "r"(s), "l"(g));
}

__device__ __forceinline__ void ldsm4(uint32_t* r, uint32_t addr) {
    asm volatile("ldmatrix.sync.aligned.m8n8.x4.shared.b16 {%0,%1,%2,%3}, [%4];"
                 : "=r"(r[0]), "=r"(r[1]), "=r"(r[2]), "=r"(r[3]) : "r"(addr));
}

__device__ __forceinline__ void ldsm4t(uint32_t* r, uint32_t addr) {
    asm volatile("ldmatrix.sync.aligned.m8n8.x4.trans.shared.b16 {%0,%1,%2,%3}, [%4];"
                 : "=r"(r[0]), "=r"(r[1]), "=r"(r[2]), "=r"(r[3]) : "r"(addr));
}

__device__ __forceinline__ void mma_f16(float* c, const uint32_t* a,
                                        uint32_t b0, uint32_t b1) {
    asm volatile(
        "mma.sync.aligned.m16n8k16.row.col.f32.f16.f16.f32 "
        "{%0,%1,%2,%3}, {%4,%5,%6,%7}, {%8,%9}, {%0,%1,%2,%3};"
        : "+f"(c[0]), "+f"(c[1]), "+f"(c[2]), "+f"(c[3])
        : "r"(a[0]), "r"(a[1]), "r"(a[2]), "r"(a[3]), "r"(b0), "r"(b1));
}

__device__ __forceinline__ uint32_t h2u(__half2 h) { return *(uint32_t*)&h; }

// ================= fp16 hi/lo split =================
__global__ __launch_bounds__(256)
void split_f16(const float4* __restrict__ src, uint2* __restrict__ hi,
               uint2* __restrict__ lo, int n4)
{
    int i = blockIdx.x * blockDim.x + threadIdx.x;
    if (i >= n4) return;
    float4 v = src[i];
    float f[4] = {v.x, v.y, v.z, v.w};
    uint32_t hh[2], ll[2];
#pragma unroll
    for (int j = 0; j < 2; j++) {
        __half2 h = __floats2half2_rn(f[2 * j], f[2 * j + 1]);
        float2 hf = __half22float2(h);
        __half2 l = __floats2half2_rn(f[2 * j] - hf.x, f[2 * j + 1] - hf.y);
        hh[j] = h2u(h);
        ll[j] = h2u(l);
    }
    hi[i] = make_uint2(hh[0], hh[1]);
    lo[i] = make_uint2(ll[0], ll[1]);
}

// ========= HMMA fp16-split GEMM: 128x64 tile, 2 CTAs/SM, dual A-stream ======
// bx < nx1 -> stream 1, else stream 2. Columns >= vs (per stream) use 2-term
// (ah*bh + ah*bl; al*bh dropped, ~2^-12 RMS) — V columns / proj only.
#define GT_AH 0
#define GT_AL 16384
#define GT_BH 32768
#define GT_BL 40960
#define G_STAGE 49152
#define GEMM_SMEM (2 * G_STAGE)

__global__ __launch_bounds__(256, 2)
void gemm_hmma(const __half* __restrict__ A1hi, const __half* __restrict__ A1lo,
               const __half* __restrict__ A2hi, const __half* __restrict__ A2lo,
               const __half* __restrict__ Bhi, const __half* __restrict__ Blo,
               float* __restrict__ C1, float* __restrict__ C2, const float* __restrict__ bias,
               __half* __restrict__ H1h, __half* __restrict__ H1l,
               __half* __restrict__ H2h, __half* __restrict__ H2l,
               int nx1, int N1, int N2, int woff2, int vs1, int vs2, int mode)
{
    extern __shared__ __align__(1024) char smem[];
    const uint32_t sb = (uint32_t)__cvta_generic_to_shared(smem);
    const int t = threadIdx.x;
    const int wid = t >> 5, lane = t & 31;
    const int m0 = blockIdx.y * 128;
    const int K = 768, NC = 12;

    const int s2 = (int)blockIdx.x >= nx1;
    const int bx = s2 ? (int)blockIdx.x - nx1 : (int)blockIdx.x;
    const int n0 = bx * 64;
    const int N = s2 ? N2 : N1;
    const int woff = s2 ? woff2 : 0;
    const int two_term = n0 >= (s2 ? vs2 : vs1);

    const int warp_m = (wid >> 1) * 32;
    const int warp_n = (wid & 1) * 32;

    float acc[2][4][4];
#pragma unroll
    for (int i = 0; i < 2; i++)
#pragma unroll
        for (int j = 0; j < 4; j++)
#pragma unroll
            for (int v = 0; v < 4; v++) acc[i][j][v] = 0.f;

    const __half* Ah = (s2 ? A2hi : A1hi) + (size_t)m0 * K;
    const __half* Al = (s2 ? A2lo : A1lo) + (size_t)m0 * K;
    const __half* Bh = Bhi + (size_t)(woff + n0) * K;
    const __half* Bl = Blo + (size_t)(woff + n0) * K;

    auto load_chunk = [&](int c, int st) {
        const int kc = c * 64;
        const uint32_t base = sb + st * G_STAGE;
#pragma unroll
        for (int i = 0; i < 4; i++) {            // A: 1024 granules, 4/thread
            const int gi = t + i * 256;
            const int row = gi >> 3, g = gi & 7;
            const uint32_t loff = (uint32_t)(row * 128 + ((g ^ (row & 7)) << 4));
            const size_t goff = (size_t)row * K + kc + g * 8;
            cp16(base + GT_AH + loff, Ah + goff);
            if (!two_term) cp16(base + GT_AL + loff, Al + goff);
        }
#pragma unroll
        for (int i = 0; i < 2; i++) {            // B: 512 granules, 2/thread
            const int gi = t + i * 256;
            const int row = gi >> 3, g = gi & 7;
            const uint32_t loff = (uint32_t)(row * 128 + ((g ^ (row & 7)) << 4));
            const size_t goff = (size_t)row * K + kc + g * 8;
            cp16(base + GT_BH + loff, Bh + goff);
            cp16(base + GT_BL + loff, Bl + goff);
        }
        asm volatile("cp.async.commit_group;");
    };

    const int fr   = lane & 15;
    const int half = lane >> 4;
    const int arow = warp_m + fr;
    const int brow = warp_n + fr;
    const int aswz = arow & 7;
    const int bswz = brow & 7;
    const uint32_t arow_off = (uint32_t)(arow * 128);
    const uint32_t brow_off = (uint32_t)(brow * 128);

    load_chunk(0, 0);

    for (int c = 0; c < NC; ++c) {
        const int st = c & 1;
        if (c + 1 < NC) {
            load_chunk(c + 1, st ^ 1);
            asm volatile("cp.async.wait_group 1;");
        } else {
            asm volatile("cp.async.wait_group 0;");
        }
        __syncthreads();

        const uint32_t base = sb + st * G_STAGE;
#pragma unroll
        for (int kk = 0; kk < 4; kk++) {
            const int kg = kk * 2 + half;
            const uint32_t aoff = arow_off + (uint32_t)((kg ^ aswz) << 4);
            const uint32_t boff = brow_off + (uint32_t)((kg ^ bswz) << 4);

            uint32_t ah[2][4], al[2][4], bh[2][4], bl[2][4];
#pragma unroll
            for (int mi = 0; mi < 2; mi++)
                ldsm4(ah[mi], base + GT_AH + aoff + mi * (16 * 128));
            if (!two_term) {
#pragma unroll
                for (int mi = 0; mi < 2; mi++)
                    ldsm4(al[mi], base + GT_AL + aoff + mi * (16 * 128));
            }
#pragma unroll
            for (int bj = 0; bj < 2; bj++) {
                ldsm4(bh[bj], base + GT_BH + boff + bj * (16 * 128));
                ldsm4(bl[bj], base + GT_BL + boff + bj * (16 * 128));
            }
#pragma unroll
            for (int mi = 0; mi < 2; mi++)
#pragma unroll
                for (int bj = 0; bj < 2; bj++) {
                    mma_f16(acc[mi][bj * 2],     ah[mi], bh[bj][0], bh[bj][2]);
                    mma_f16(acc[mi][bj * 2 + 1], ah[mi], bh[bj][1], bh[bj][3]);
                }
#pragma unroll
            for (int mi = 0; mi < 2; mi++)
#pragma unroll
                for (int bj = 0; bj < 2; bj++) {
                    mma_f16(acc[mi][bj * 2],     ah[mi], bl[bj][0], bl[bj][2]);
                    mma_f16(acc[mi][bj * 2 + 1], ah[mi], bl[bj][1], bl[bj][3]);
                }
            if (!two_term) {
#pragma unroll
                for (int mi = 0; mi < 2; mi++)
#pragma unroll
                    for (int bj = 0; bj < 2; bj++) {
                        mma_f16(acc[mi][bj * 2],     al[mi], bh[bj][0], bh[bj][2]);
                        mma_f16(acc[mi][bj * 2 + 1], al[mi], bh[bj][1], bh[bj][3]);
                    }
            }
        }
        __syncthreads();
    }

    float* C = s2 ? C2 : C1;
    __half* Hh = s2 ? H2h : H1h;
    __half* Hl = s2 ? H2l : H1l;
#pragma unroll
    for (int mi = 0; mi < 2; mi++) {
        const int r = m0 + warp_m + mi * 16 + (lane >> 2);
#pragma unroll
        for (int j = 0; j < 4; j++) {
            const int col = n0 + warp_n + j * 8 + (lane & 3) * 2;
            float v00 = acc[mi][j][0], v01 = acc[mi][j][1];
            float v10 = acc[mi][j][2], v11 = acc[mi][j][3];
            if (mode == 0) {
                const float b0 = bias[col], b1 = bias[col + 1];
                *(float2*)(C + (size_t)r * N + col)       = make_float2(v00 + b0, v01 + b1);
                *(float2*)(C + (size_t)(r + 8) * N + col) = make_float2(v10 + b0, v11 + b1);
            } else {
                __half h00 = __float2half_rn(v00), h01 = __float2half_rn(v01);
                __half h10 = __float2half_rn(v10), h11 = __float2half_rn(v11);
                __half l00 = __float2half_rn(v00 - __half2float(h00));
                __half l01 = __float2half_rn(v01 - __half2float(h01));
                __half l10 = __float2half_rn(v10 - __half2float(h10));
                __half l11 = __float2half_rn(v11 - __half2float(h11));
                const size_t o0 = (size_t)r * N + col;
                const size_t o1 = (size_t)(r + 8) * N + col;
                *(ushort2*)(Hh + o0) = make_ushort2(__half_as_ushort(h00), __half_as_ushort(h01));
                *(ushort2*)(Hl + o0) = make_ushort2(__half_as_ushort(l00), __half_as_ushort(l01));
                *(ushort2*)(Hh + o1) = make_ushort2(__half_as_ushort(h10), __half_as_ushort(h11));
                *(ushort2*)(Hl + o1) = make_ushort2(__half_as_ushort(l10), __half_as_ushort(l11));
            }
        }
    }
}

// ======= HMMA flash attention: 2 CTAs/SM, merged branches, PV 2-term =========
#define ATT_QH 0
#define ATT_QL 16384
#define ATT_KV 32768
#define ATT_KV_STAGE 32768
#define ATT_SMEM 98304
#define ATT_KHo 0
#define ATT_KLo 8192
#define ATT_VHo 16384
#define ATT_VLo 24576

__global__ __launch_bounds__(256, 2)
void attn_hmma(const __half* __restrict__ Qh, const __half* __restrict__ Ql, int ldq,
               const __half* __restrict__ K1h, const __half* __restrict__ K1l,
               const __half* __restrict__ V1h, const __half* __restrict__ V1l, int ld1,
               const __half* __restrict__ K2h, const __half* __restrict__ K2l,
               const __half* __restrict__ V2h, const __half* __restrict__ V2l, int ld2,
               __half* __restrict__ O1hi, __half* __restrict__ O1lo,
               __half* __restrict__ O2hi, __half* __restrict__ O2lo)
{
    extern __shared__ __align__(1024) char smem[];
    const uint32_t sb = (uint32_t)__cvta_generic_to_shared(smem);
    const int t = threadIdx.x;
    const int lane = t & 31, wid = t >> 5;
    const int warp_m = wid * 16;
    const int bh = blockIdx.y;
    const int br = blockIdx.z;
    const int b = bh / 12, h = bh % 12;
    const int q0 = blockIdx.x * 128;
    const size_t rowbase = (size_t)b * 1024;

    const int ldkv = br ? ld2 : ld1;
    const __half* Kph = (br ? K2h : K1h) + rowbase * ldkv + h * 64;
    const __half* Kpl = (br ? K2l : K1l) + rowbase * ldkv + h * 64;
    const __half* Vph = (br ? V2h : V1h) + rowbase * ldkv + h * 64;
    const __half* Vpl = (br ? V2l : V1l) + rowbase * ldkv + h * 64;
    __half* Ohi = br ? O2hi : O1hi;
    __half* Olo = br ? O2lo : O1lo;
    const __half* Qph = Qh + (rowbase + q0) * ldq + h * 64;
    const __half* Qpl = Ql + (rowbase + q0) * ldq + h * 64;

    auto load_kv = [&](int c, int st) {
        const int k0 = c * 64;
        const uint32_t base = sb + ATT_KV + st * ATT_KV_STAGE;
#pragma unroll
        for (int i = 0; i < 8; i++) {
            const int idx = t + i * 256;
            const int sel = i >> 1;             // 0:KH 1:KL 2:VH 3:VL
            const int r = (idx >> 3) & 63, g = idx & 7;
            const __half* src = (sel == 0 ? Kph : sel == 1 ? Kpl
                                 : sel == 2 ? Vph : Vpl) + (size_t)(k0 + r) * ldkv + g * 8;
            const uint32_t off = base + sel * 8192 +
                                 (uint32_t)(r * 128 + ((g ^ (r & 7)) << 4));
            cp16(off, src);
        }
    };

#pragma unroll
    for (int i = 0; i < 8; i++) {
        const int idx = t + i * 256;
        const int sel = i >> 2;                 // 0:QH 1:QL
        const int r = (idx >> 3) & 127, g = idx & 7;
        const __half* src = (sel ? Qpl : Qph) + (size_t)r * ldq + g * 8;
        const uint32_t off = sb + (sel ? ATT_QL : ATT_QH) +
                             (uint32_t)(r * 128 + ((g ^ (r & 7)) << 4));
        cp16(off, src);
    }
    load_kv(0, 0);
    asm volatile("cp.async.commit_group;");

    float m_i[2], l_i[2], accO[8][4];
    m_i[0] = m_i[1] = -1e30f;
    l_i[0] = l_i[1] = 0.f;
#pragma unroll
    for (int f = 0; f < 8; f++)
#pragma unroll
        for (int v = 0; v < 4; v++) accO[f][v] = 0.f;

    const int f16  = lane & 15;
    const int gsel = lane >> 4;
    const int qrow = warp_m + f16;
    const uint32_t q_off = (uint32_t)(qrow * 128);
    const int qswz = qrow & 7;
    const int kswz = f16 & 7;
    const int vrow_l = (lane & 7) + 8 * ((lane >> 3) & 1);
    const int vswz = vrow_l & 7;

    for (int c = 0; c < 16; ++c) {
        const int st = c & 1;
        asm volatile("cp.async.wait_group 0;");
        __syncthreads();
        const uint32_t kvb = sb + ATT_KV + st * ATT_KV_STAGE;

        float sf[8][4];
#pragma unroll
        for (int f = 0; f < 8; f++)
#pragma unroll
            for (int v = 0; v < 4; v++) sf[f][v] = 0.f;

#pragma unroll
        for (int ks = 0; ks < 4; ks++) {
            const int kg = 2 * ks + gsel;
            uint32_t qh[4], ql[4];
            const uint32_t qa = sb + q_off + (uint32_t)((kg ^ qswz) << 4);
            ldsm4(qh, ATT_QH + qa);
            ldsm4(ql, ATT_QL + qa);

            uint32_t kh[4][4], kl[4][4];
#pragma unroll
            for (int np = 0; np < 4; np++) {
                const uint32_t ka = kvb + (uint32_t)((np * 16 + f16) * 128) +
                                    (uint32_t)((kg ^ kswz) << 4);
                ldsm4(kh[np], ATT_KHo + ka);
                ldsm4(kl[np], ATT_KLo + ka);
            }
#pragma unroll
            for (int np = 0; np < 4; np++) {
                mma_f16(sf[2 * np],     qh, kh[np][0], kh[np][2]);
                mma_f16(sf[2 * np + 1], qh, kh[np][1], kh[np][3]);
            }
#pragma unroll
            for (int np = 0; np < 4; np++) {
                mma_f16(sf[2 * np],     qh, kl[np][0], kl[np][2]);
                mma_f16(sf[2 * np + 1], qh, kl[np][1], kl[np][3]);
            }
#pragma unroll
            for (int np = 0; np < 4; np++) {
                mma_f16(sf[2 * np],     ql, kh[np][0], kh[np][2]);
                mma_f16(sf[2 * np + 1], ql, kh[np][1], kh[np][3]);
            }
        }

        if (c + 1 < 16) {
            load_kv(c + 1, st ^ 1);
            asm volatile("cp.async.commit_group;");
        }

        float mx0 = -1e30f, mx1 = -1e30f;
#pragma unroll
        for (int f = 0; f < 8; f++) {
            sf[f][0] *= 0.125f; sf[f][1] *= 0.125f;
            sf[f][2] *= 0.125f; sf[f][3] *= 0.125f;
            mx0 = fmaxf(mx0, fmaxf(sf[f][0], sf[f][1]));
            mx1 = fmaxf(mx1, fmaxf(sf[f][2], sf[f][3]));
        }
        mx0 = fmaxf(mx0, __shfl_xor_sync(0xffffffffu, mx0, 1));
        mx0 = fmaxf(mx0, __shfl_xor_sync(0xffffffffu, mx0, 2));
        mx1 = fmaxf(mx1, __shfl_xor_sync(0xffffffffu, mx1, 1));
        mx1 = fmaxf(mx1, __shfl_xor_sync(0xffffffffu, mx1, 2));

        const float mn0 = fmaxf(m_i[0], mx0);
        const float mn1 = fmaxf(m_i[1], mx1);
        const float al0 = __expf(m_i[0] - mn0);
        const float al1 = __expf(m_i[1] - mn1);
        m_i[0] = mn0; m_i[1] = mn1;

        float sum0 = 0.f, sum1 = 0.f;
#pragma unroll
        for (int f = 0; f < 8; f++) {
            sf[f][0] = __expf(sf[f][0] - mn0);
            sf[f][1] = __expf(sf[f][1] - mn0);
            sf[f][2] = __expf(sf[f][2] - mn1);
            sf[f][3] = __expf(sf[f][3] - mn1);
            sum0 += sf[f][0] + sf[f][1];
            sum1 += sf[f][2] + sf[f][3];
        }
        sum0 += __shfl_xor_sync(0xffffffffu, sum0, 1);
        sum0 += __shfl_xor_sync(0xffffffffu, sum0, 2);
        sum1 += __shfl_xor_sync(0xffffffffu, sum1, 1);
        sum1 += __shfl_xor_sync(0xffffffffu, sum1, 2);
        l_i[0] = l_i[0] * al0 + sum0;
        l_i[1] = l_i[1] * al1 + sum1;

#pragma unroll
        for (int f = 0; f < 8; f++) {
            accO[f][0] *= al0; accO[f][1] *= al0;
            accO[f][2] *= al1; accO[f][3] *= al1;
        }

        // ---- O += P V (2-term: ph*vh + ph*vl) ----
#pragma unroll
        for (int ks = 0; ks < 4; ks++) {
            const int f0 = 2 * ks, f1 = 2 * ks + 1;
            uint32_t ah[4];
            ah[0] = h2u(__floats2half2_rn(sf[f0][0], sf[f0][1]));
            ah[1] = h2u(__floats2half2_rn(sf[f0][2], sf[f0][3]));
            ah[2] = h2u(__floats2half2_rn(sf[f1][0], sf[f1][1]));
            ah[3] = h2u(__floats2half2_rn(sf[f1][2], sf[f1][3]));

            const int vrow = ks * 16 + vrow_l;
            uint32_t vh[4][4], vl[4][4];
#pragma unroll
            for (int g2 = 0; g2 < 4; g2++) {
                const int vg = 2 * g2 + gsel;
                const uint32_t va = kvb + (uint32_t)(vrow * 128) +
                                    (uint32_t)((vg ^ vswz) << 4);
                ldsm4t(vh[g2], ATT_VHo + va);
                ldsm4t(vl[g2], ATT_VLo + va);
            }
#pragma unroll
            for (int g2 = 0; g2 < 4; g2++) {
                mma_f16(accO[2 * g2],     ah, vh[g2][0], vh[g2][1]);
                mma_f16(accO[2 * g2 + 1], ah, vh[g2][2], vh[g2][3]);
            }
#pragma unroll
            for (int g2 = 0; g2 < 4; g2++) {
                mma_f16(accO[2 * g2],     ah, vl[g2][0], vl[g2][1]);
                mma_f16(accO[2 * g2 + 1], ah, vl[g2][2], vl[g2][3]);
            }
        }
    }

    // ---- epilogue: normalize + fp16 hi/lo split (feeds proj GEMM) ----
    const float inv0 = 1.f / l_i[0];
    const float inv1 = 1.f / l_i[1];
    const size_t r0 = rowbase + q0 + warp_m + (lane >> 2);
    const size_t r1 = r0 + 8;
    const int colb = h * 64 + (lane & 3) * 2;
#pragma unroll
    for (int f = 0; f < 8; f++) {
        float v00 = accO[f][0] * inv0, v01 = accO[f][1] * inv0;
        float v10 = accO[f][2] * inv1, v11 = accO[f][3] * inv1;
        __half h00 = __float2half_rn(v00), h01 = __float2half_rn(v01);
        __half h10 = __float2half_rn(v10), h11 = __float2half_rn(v11);
        __half l00 = __float2half_rn(v00 - __half2float(h00));
        __half l01 = __float2half_rn(v01 - __half2float(h01));
        __half l10 = __float2half_rn(v10 - __half2float(h10));
        __half l11 = __float2half_rn(v11 - __half2float(h11));
        const size_t o0 = r0 * 768 + colb + 8 * f;
        const size_t o1 = r1 * 768 + colb + 8 * f;
        *(ushort2*)(Ohi + o0) = make_ushort2(__half_as_ushort(h00), __half_as_ushort(h01));
        *(ushort2*)(Olo + o0) = make_ushort2(__half_as_ushort(l00), __half_as_ushort(l01));
        *(ushort2*)(Ohi + o1) = make_ushort2(__half_as_ushort(h10), __half_as_ushort(h11));
        *(ushort2*)(Olo + o1) = make_ushort2(__half_as_ushort(l10), __half_as_ushort(l11));
    }
}

// ================= launch =================
extern "C" void kernel_launch(void* const* d_in, const int* in_sizes, int n_in,
                              void* d_out, int out_size)
{
    const float* x      = (const float*)d_in[0];
    const float* x2     = (const float*)d_in[1];
    const float* qkv_w  = (const float*)d_in[2];
    const float* proj_w = (const float*)d_in[3];
    const float* proj_b = (const float*)d_in[4];
    float* out = (float*)d_out;

    __half *qkvh, *qkvl, *kv2h, *kv2l;
    __half *xhi, *xlo, *x2hi, *x2lo, *wqhi, *wqlo, *wphi, *wplo;
    __half *o1hi, *o1lo, *o2hi, *o2lo;
    cudaGetSymbolAddress((void**)&qkvh, g_qkvh);
    cudaGetSymbolAddress((void**)&qkvl, g_qkvl);
    cudaGetSymbolAddress((void**)&kv2h, g_kv2h);
    cudaGetSymbolAddress((void**)&kv2l, g_kv2l);
    cudaGetSymbolAddress((void**)&xhi,  g_xhi);
    cudaGetSymbolAddress((void**)&xlo,  g_xlo);
    cudaGetSymbolAddress((void**)&x2hi, g_x2hi);
    cudaGetSymbolAddress((void**)&x2lo, g_x2lo);
    cudaGetSymbolAddress((void**)&wqhi, g_wqhi);
    cudaGetSymbolAddress((void**)&wqlo, g_wqlo);
    cudaGetSymbolAddress((void**)&wphi, g_wphi);
    cudaGetSymbolAddress((void**)&wplo, g_wplo);
    cudaGetSymbolAddress((void**)&o1hi, g_o1hi);
    cudaGetSymbolAddress((void**)&o1lo, g_o1lo);
    cudaGetSymbolAddress((void**)&o2hi, g_o2hi);
    cudaGetSymbolAddress((void**)&o2lo, g_o2lo);

    cudaFuncSetAttribute(gemm_hmma, cudaFuncAttributeMaxDynamicSharedMemorySize, GEMM_SMEM);
    cudaFuncSetAttribute(attn_hmma, cudaFuncAttributeMaxDynamicSharedMemorySize, ATT_SMEM);

    const int M = 8192;

    {
        int n4 = 8192 * 768 / 4;
        split_f16<<<n4 / 256, 256>>>((const float4*)x,  (uint2*)xhi,  (uint2*)xlo,  n4);
        split_f16<<<n4 / 256, 256>>>((const float4*)x2, (uint2*)x2hi, (uint2*)x2lo, n4);
    }
    {
        int n4 = 2304 * 768 / 4;
        split_f16<<<n4 / 256, 256>>>((const float4*)qkv_w, (uint2*)wqhi, (uint2*)wqlo, n4);
    }
    {
        int n4 = 768 * 768 / 4;
        split_f16<<<n4 / 256, 256>>>((const float4*)proj_w, (uint2*)wphi, (uint2*)wplo, n4);
    }

    // QKV (x, 36 n-tiles) + KV2 (x2, 24 n-tiles); V / V2 columns use 2-term
    gemm_hmma<<<dim3(60, M / 128), 256, GEMM_SMEM>>>(
        xhi, xlo, x2hi, x2lo, wqhi, wqlo,
        nullptr, nullptr, nullptr,
        qkvh, qkvl, kv2h, kv2l,
        36, 2304, 1536, 768, /*vs1=*/1536, /*vs2=*/768, 1);

    // both attention branches in one launch (z = branch)
    attn_hmma<<<dim3(8, 96, 2), 256, ATT_SMEM>>>(
        qkvh, qkvl, 2304,
        qkvh + 768, qkvl + 768, qkvh + 1536, qkvl + 1536, 2304,
        kv2h, kv2l, kv2h + 768, kv2l + 768, 1536,
        o1hi, o1lo, o2hi, o2lo);

    // both output projections (+bias), all 2-term
    gemm_hmma<<<dim3(24, M / 128), 256, GEMM_SMEM>>>(
        o1hi, o1lo, o2hi, o2lo, wphi, wplo,
        out, out + (size_t)M * 768, proj_b,
        nullptr, nullptr, nullptr, nullptr,
        12, 768, 768, 0, /*vs1=*/0, /*vs2=*/0, 0);
}

// round 16
// speedup vs baseline: 1.4205x; 1.1312x over previous
#include <cuda_runtime.h>
#include <cuda_fp16.h>
#include <cstdint>

// ================= scratch (no allocations allowed) =================
__device__ __align__(256) __half g_qkvh[8192 * 2304], g_qkvl[8192 * 2304]; // q|k|v fp16 hi/lo
__device__ __align__(256) __half g_kv2h[8192 * 1536], g_kv2l[8192 * 1536]; // k2|v2 fp16 hi/lo

__device__ __align__(256) __half g_xhi[8192 * 768],  g_xlo[8192 * 768];
__device__ __align__(256) __half g_x2hi[8192 * 768], g_x2lo[8192 * 768];
__device__ __align__(256) __half g_wqhi[2304 * 768], g_wqlo[2304 * 768];
__device__ __align__(256) __half g_wphi[768 * 768],  g_wplo[768 * 768];
__device__ __align__(256) __half g_o1hi[8192 * 768], g_o1lo[8192 * 768];
__device__ __align__(256) __half g_o2hi[8192 * 768], g_o2lo[8192 * 768];

// ================= helpers =================
__device__ __forceinline__ void cp16(uint32_t s, const void* g) {
    asm volatile("cp.async.cg.shared.global [%0], [%1], 16;" :: "r"(s), "l"(g));
}

__device__ __forceinline__ void ldsm4(uint32_t* r, uint32_t addr) {
    asm volatile("ldmatrix.sync.aligned.m8n8.x4.shared.b16 {%0,%1,%2,%3}, [%4];"
                 : "=r"(r[0]), "=r"(r[1]), "=r"(r[2]), "=r"(r[3]) : "r"(addr));
}

__device__ __forceinline__ void ldsm4t(uint32_t* r, uint32_t addr) {
    asm volatile("ldmatrix.sync.aligned.m8n8.x4.trans.shared.b16 {%0,%1,%2,%3}, [%4];"
                 : "=r"(r[0]), "=r"(r[1]), "=r"(r[2]), "=r"(r[3]) : "r"(addr));
}

__device__ __forceinline__ void mma_f16(float* c, const uint32_t* a,
                                        uint32_t b0, uint32_t b1) {
    asm volatile(
        "mma.sync.aligned.m16n8k16.row.col.f32.f16.f16.f32 "
        "{%0,%1,%2,%3}, {%4,%5,%6,%7}, {%8,%9}, {%0,%1,%2,%3};"
        : "+f"(c[0]), "+f"(c[1]), "+f"(c[2]), "+f"(c[3])
        : "r"(a[0]), "r"(a[1]), "r"(a[2]), "r"(a[3]), "r"(b0), "r"(b1));
}

__device__ __forceinline__ uint32_t h2u(__half2 h) { return *(uint32_t*)&h; }

// ================= fp16 hi/lo split =================
__global__ __launch_bounds__(256)
void split_f16(const float4* __restrict__ src, uint2* __restrict__ hi,
               uint2* __restrict__ lo, int n4)
{
    int i = blockIdx.x * blockDim.x + threadIdx.x;
    if (i >= n4) return;
    float4 v = src[i];
    float f[4] = {v.x, v.y, v.z, v.w};
    uint32_t hh[2], ll[2];
#pragma unroll
    for (int j = 0; j < 2; j++) {
        __half2 h = __floats2half2_rn(f[2 * j], f[2 * j + 1]);
        float2 hf = __half22float2(h);
        __half2 l = __floats2half2_rn(f[2 * j] - hf.x, f[2 * j + 1] - hf.y);
        hh[j] = h2u(h);
        ll[j] = h2u(l);
    }
    hi[i] = make_uint2(hh[0], hh[1]);
    lo[i] = make_uint2(ll[0], ll[1]);
}

// ========= HMMA fp16-split GEMM: 128x64 tile, 2 CTAs/SM, dual A-stream ======
// bx < nx1 -> stream 1, else stream 2. Columns >= vs (per stream) use 2-term
// (ah*bh + ah*bl; al*bh dropped, ~2^-12 RMS).
#define GT_AH 0
#define GT_AL 16384
#define GT_BH 32768
#define GT_BL 40960
#define G_STAGE 49152
#define GEMM_SMEM (2 * G_STAGE)

__global__ __launch_bounds__(256, 2)
void gemm_hmma(const __half* __restrict__ A1hi, const __half* __restrict__ A1lo,
               const __half* __restrict__ A2hi, const __half* __restrict__ A2lo,
               const __half* __restrict__ Bhi, const __half* __restrict__ Blo,
               float* __restrict__ C1, float* __restrict__ C2, const float* __restrict__ bias,
               __half* __restrict__ H1h, __half* __restrict__ H1l,
               __half* __restrict__ H2h, __half* __restrict__ H2l,
               int nx1, int N1, int N2, int woff2, int vs1, int vs2, int mode)
{
    extern __shared__ __align__(1024) char smem[];
    const uint32_t sb = (uint32_t)__cvta_generic_to_shared(smem);
    const int t = threadIdx.x;
    const int wid = t >> 5, lane = t & 31;
    const int m0 = blockIdx.y * 128;
    const int K = 768, NC = 12;

    const int s2 = (int)blockIdx.x >= nx1;
    const int bx = s2 ? (int)blockIdx.x - nx1 : (int)blockIdx.x;
    const int n0 = bx * 64;
    const int N = s2 ? N2 : N1;
    const int woff = s2 ? woff2 : 0;
    const int two_term = n0 >= (s2 ? vs2 : vs1);

    const int warp_m = (wid >> 1) * 32;
    const int warp_n = (wid & 1) * 32;

    float acc[2][4][4];
#pragma unroll
    for (int i = 0; i < 2; i++)
#pragma unroll
        for (int j = 0; j < 4; j++)
#pragma unroll
            for (int v = 0; v < 4; v++) acc[i][j][v] = 0.f;

    const __half* Ah = (s2 ? A2hi : A1hi) + (size_t)m0 * K;
    const __half* Al = (s2 ? A2lo : A1lo) + (size_t)m0 * K;
    const __half* Bh = Bhi + (size_t)(woff + n0) * K;
    const __half* Bl = Blo + (size_t)(woff + n0) * K;

    auto load_chunk = [&](int c, int st) {
        const int kc = c * 64;
        const uint32_t base = sb + st * G_STAGE;
#pragma unroll
        for (int i = 0; i < 4; i++) {            // A: 1024 granules, 4/thread
            const int gi = t + i * 256;
            const int row = gi >> 3, g = gi & 7;
            const uint32_t loff = (uint32_t)(row * 128 + ((g ^ (row & 7)) << 4));
            const size_t goff = (size_t)row * K + kc + g * 8;
            cp16(base + GT_AH + loff, Ah + goff);
            if (!two_term) cp16(base + GT_AL + loff, Al + goff);
        }
#pragma unroll
        for (int i = 0; i < 2; i++) {            // B: 512 granules, 2/thread
            const int gi = t + i * 256;
            const int row = gi >> 3, g = gi & 7;
            const uint32_t loff = (uint32_t)(row * 128 + ((g ^ (row & 7)) << 4));
            const size_t goff = (size_t)row * K + kc + g * 8;
            cp16(base + GT_BH + loff, Bh + goff);
            cp16(base + GT_BL + loff, Bl + goff);
        }
        asm volatile("cp.async.commit_group;");
    };

    const int fr   = lane & 15;
    const int half = lane >> 4;
    const int arow = warp_m + fr;
    const int brow = warp_n + fr;
    const int aswz = arow & 7;
    const int bswz = brow & 7;
    const uint32_t arow_off = (uint32_t)(arow * 128);
    const uint32_t brow_off = (uint32_t)(brow * 128);

    load_chunk(0, 0);

    for (int c = 0; c < NC; ++c) {
        const int st = c & 1;
        if (c + 1 < NC) {
            load_chunk(c + 1, st ^ 1);
            asm volatile("cp.async.wait_group 1;");
        } else {
            asm volatile("cp.async.wait_group 0;");
        }
        __syncthreads();

        const uint32_t base = sb + st * G_STAGE;
#pragma unroll
        for (int kk = 0; kk < 4; kk++) {
            const int kg = kk * 2 + half;
            const uint32_t aoff = arow_off + (uint32_t)((kg ^ aswz) << 4);
            const uint32_t boff = brow_off + (uint32_t)((kg ^ bswz) << 4);

            uint32_t ah[2][4], al[2][4], bh[2][4], bl[2][4];
#pragma unroll
            for (int mi = 0; mi < 2; mi++)
                ldsm4(ah[mi], base + GT_AH + aoff + mi * (16 * 128));
            if (!two_term) {
#pragma unroll
                for (int mi = 0; mi < 2; mi++)
                    ldsm4(al[mi], base + GT_AL + aoff + mi * (16 * 128));
            }
#pragma unroll
            for (int bj = 0; bj < 2; bj++) {
                ldsm4(bh[bj], base + GT_BH + boff + bj * (16 * 128));
                ldsm4(bl[bj], base + GT_BL + boff + bj * (16 * 128));
            }
#pragma unroll
            for (int mi = 0; mi < 2; mi++)
#pragma unroll
                for (int bj = 0; bj < 2; bj++) {
                    mma_f16(acc[mi][bj * 2],     ah[mi], bh[bj][0], bh[bj][2]);
                    mma_f16(acc[mi][bj * 2 + 1], ah[mi], bh[bj][1], bh[bj][3]);
                }
#pragma unroll
            for (int mi = 0; mi < 2; mi++)
#pragma unroll
                for (int bj = 0; bj < 2; bj++) {
                    mma_f16(acc[mi][bj * 2],     ah[mi], bl[bj][0], bl[bj][2]);
                    mma_f16(acc[mi][bj * 2 + 1], ah[mi], bl[bj][1], bl[bj][3]);
                }
            if (!two_term) {
#pragma unroll
                for (int mi = 0; mi < 2; mi++)
#pragma unroll
                    for (int bj = 0; bj < 2; bj++) {
                        mma_f16(acc[mi][bj * 2],     al[mi], bh[bj][0], bh[bj][2]);
                        mma_f16(acc[mi][bj * 2 + 1], al[mi], bh[bj][1], bh[bj][3]);
                    }
            }
        }
        __syncthreads();
    }

    float* C = s2 ? C2 : C1;
    __half* Hh = s2 ? H2h : H1h;
    __half* Hl = s2 ? H2l : H1l;
#pragma unroll
    for (int mi = 0; mi < 2; mi++) {
        const int r = m0 + warp_m + mi * 16 + (lane >> 2);
#pragma unroll
        for (int j = 0; j < 4; j++) {
            const int col = n0 + warp_n + j * 8 + (lane & 3) * 2;
            float v00 = acc[mi][j][0], v01 = acc[mi][j][1];
            float v10 = acc[mi][j][2], v11 = acc[mi][j][3];
            if (mode == 0) {
                const float b0 = bias[col], b1 = bias[col + 1];
                *(float2*)(C + (size_t)r * N + col)       = make_float2(v00 + b0, v01 + b1);
                *(float2*)(C + (size_t)(r + 8) * N + col) = make_float2(v10 + b0, v11 + b1);
            } else {
                __half h00 = __float2half_rn(v00), h01 = __float2half_rn(v01);
                __half h10 = __float2half_rn(v10), h11 = __float2half_rn(v11);
                __half l00 = __float2half_rn(v00 - __half2float(h00));
                __half l01 = __float2half_rn(v01 - __half2float(h01));
                __half l10 = __float2half_rn(v10 - __half2float(h10));
                __half l11 = __float2half_rn(v11 - __half2float(h11));
                const size_t o0 = (size_t)r * N + col;
                const size_t o1 = (size_t)(r + 8) * N + col;
                *(ushort2*)(Hh + o0) = make_ushort2(__half_as_ushort(h00), __half_as_ushort(h01));
                *(ushort2*)(Hl + o0) = make_ushort2(__half_as_ushort(l00), __half_as_ushort(l01));
                *(ushort2*)(Hh + o1) = make_ushort2(__half_as_ushort(h10), __half_as_ushort(h11));
                *(ushort2*)(Hl + o1) = make_ushort2(__half_as_ushort(l10), __half_as_ushort(l11));
            }
        }
    }
}

// == HMMA flash attention: 2 CTAs/SM, merged branches, QK+PV both 2-term ======
// QK = qh*kh + qh*kl (Q_lo never loaded). PV = ph*vh + ph*vl.
#define ATT_QH 0
#define ATT_KV 32768
#define ATT_KV_STAGE 32768
#define ATT_SMEM 98304
#define ATT_KHo 0
#define ATT_KLo 8192
#define ATT_VHo 16384
#define ATT_VLo 24576

__global__ __launch_bounds__(256, 2)
void attn_hmma(const __half* __restrict__ Qh, int ldq,
               const __half* __restrict__ K1h, const __half* __restrict__ K1l,
               const __half* __restrict__ V1h, const __half* __restrict__ V1l, int ld1,
               const __half* __restrict__ K2h, const __half* __restrict__ K2l,
               const __half* __restrict__ V2h, const __half* __restrict__ V2l, int ld2,
               __half* __restrict__ O1hi, __half* __restrict__ O1lo,
               __half* __restrict__ O2hi, __half* __restrict__ O2lo)
{
    extern __shared__ __align__(1024) char smem[];
    const uint32_t sb = (uint32_t)__cvta_generic_to_shared(smem);
    const int t = threadIdx.x;
    const int lane = t & 31, wid = t >> 5;
    const int warp_m = wid * 16;
    const int bh = blockIdx.y;
    const int br = blockIdx.z;
    const int b = bh / 12, h = bh % 12;
    const int q0 = blockIdx.x * 128;
    const size_t rowbase = (size_t)b * 1024;

    const int ldkv = br ? ld2 : ld1;
    const __half* Kph = (br ? K2h : K1h) + rowbase * ldkv + h * 64;
    const __half* Kpl = (br ? K2l : K1l) + rowbase * ldkv + h * 64;
    const __half* Vph = (br ? V2h : V1h) + rowbase * ldkv + h * 64;
    const __half* Vpl = (br ? V2l : V1l) + rowbase * ldkv + h * 64;
    __half* Ohi = br ? O2hi : O1hi;
    __half* Olo = br ? O2lo : O1lo;
    const __half* Qph = Qh + (rowbase + q0) * ldq + h * 64;

    auto load_kv = [&](int c, int st) {
        const int k0 = c * 64;
        const uint32_t base = sb + ATT_KV + st * ATT_KV_STAGE;
#pragma unroll
        for (int i = 0; i < 8; i++) {
            const int idx = t + i * 256;
            const int sel = i >> 1;             // 0:KH 1:KL 2:VH 3:VL
            const int r = (idx >> 3) & 63, g = idx & 7;
            const __half* src = (sel == 0 ? Kph : sel == 1 ? Kpl
                                 : sel == 2 ? Vph : Vpl) + (size_t)(k0 + r) * ldkv + g * 8;
            const uint32_t off = base + sel * 8192 +
                                 (uint32_t)(r * 128 + ((g ^ (r & 7)) << 4));
            cp16(off, src);
        }
    };

    // prologue: Q hi only (1024 granules) + chunk 0
#pragma unroll
    for (int i = 0; i < 4; i++) {
        const int idx = t + i * 256;
        const int r = idx >> 3, g = idx & 7;
        const __half* src = Qph + (size_t)r * ldq + g * 8;
        const uint32_t off = sb + ATT_QH +
                             (uint32_t)(r * 128 + ((g ^ (r & 7)) << 4));
        cp16(off, src);
    }
    load_kv(0, 0);
    asm volatile("cp.async.commit_group;");

    float m_i[2], l_i[2], accO[8][4];
    m_i[0] = m_i[1] = -1e30f;
    l_i[0] = l_i[1] = 0.f;
#pragma unroll
    for (int f = 0; f < 8; f++)
#pragma unroll
        for (int v = 0; v < 4; v++) accO[f][v] = 0.f;

    const int f16  = lane & 15;
    const int gsel = lane >> 4;
    const int qrow = warp_m + f16;
    const uint32_t q_off = (uint32_t)(qrow * 128);
    const int qswz = qrow & 7;
    const int kswz = f16 & 7;
    const int vrow_l = (lane & 7) + 8 * ((lane >> 3) & 1);
    const int vswz = vrow_l & 7;

    for (int c = 0; c < 16; ++c) {
        const int st = c & 1;
        asm volatile("cp.async.wait_group 0;");
        __syncthreads();
        const uint32_t kvb = sb + ATT_KV + st * ATT_KV_STAGE;

        float sf[8][4];
#pragma unroll
        for (int f = 0; f < 8; f++)
#pragma unroll
            for (int v = 0; v < 4; v++) sf[f][v] = 0.f;

#pragma unroll
        for (int ks = 0; ks < 4; ks++) {
            const int kg = 2 * ks + gsel;
            uint32_t qh[4];
            const uint32_t qa = sb + q_off + (uint32_t)((kg ^ qswz) << 4);
            ldsm4(qh, ATT_QH + qa);

            uint32_t kh[4][4], kl[4][4];
#pragma unroll
            for (int np = 0; np < 4; np++) {
                const uint32_t ka = kvb + (uint32_t)((np * 16 + f16) * 128) +
                                    (uint32_t)((kg ^ kswz) << 4);
                ldsm4(kh[np], ATT_KHo + ka);
                ldsm4(kl[np], ATT_KLo + ka);
            }
#pragma unroll
            for (int np = 0; np < 4; np++) {
                mma_f16(sf[2 * np],     qh, kh[np][0], kh[np][2]);
                mma_f16(sf[2 * np + 1], qh, kh[np][1], kh[np][3]);
            }
#pragma unroll
            for (int np = 0; np < 4; np++) {
                mma_f16(sf[2 * np],     qh, kl[np][0], kl[np][2]);
                mma_f16(sf[2 * np + 1], qh, kl[np][1], kl[np][3]);
            }
        }

        if (c + 1 < 16) {
            load_kv(c + 1, st ^ 1);
            asm volatile("cp.async.commit_group;");
        }

        float mx0 = -1e30f, mx1 = -1e30f;
#pragma unroll
        for (int f = 0; f < 8; f++) {
            sf[f][0] *= 0.125f; sf[f][1] *= 0.125f;
            sf[f][2] *= 0.125f; sf[f][3] *= 0.125f;
            mx0 = fmaxf(mx0, fmaxf(sf[f][0], sf[f][1]));
            mx1 = fmaxf(mx1, fmaxf(sf[f][2], sf[f][3]));
        }
        mx0 = fmaxf(mx0, __shfl_xor_sync(0xffffffffu, mx0, 1));
        mx0 = fmaxf(mx0, __shfl_xor_sync(0xffffffffu, mx0, 2));
        mx1 = fmaxf(mx1, __shfl_xor_sync(0xffffffffu, mx1, 1));
        mx1 = fmaxf(mx1, __shfl_xor_sync(0xffffffffu, mx1, 2));

        const float mn0 = fmaxf(m_i[0], mx0);
        const float mn1 = fmaxf(m_i[1], mx1);
        const float al0 = __expf(m_i[0] - mn0);
        const float al1 = __expf(m_i[1] - mn1);
        m_i[0] = mn0; m_i[1] = mn1;

        float sum0 = 0.f, sum1 = 0.f;
#pragma unroll
        for (int f = 0; f < 8; f++) {
            sf[f][0] = __expf(sf[f][0] - mn0);
            sf[f][1] = __expf(sf[f][1] - mn0);
            sf[f][2] = __expf(sf[f][2] - mn1);
            sf[f][3] = __expf(sf[f][3] - mn1);
            sum0 += sf[f][0] + sf[f][1];
            sum1 += sf[f][2] + sf[f][3];
        }
        sum0 += __shfl_xor_sync(0xffffffffu, sum0, 1);
        sum0 += __shfl_xor_sync(0xffffffffu, sum0, 2);
        sum1 += __shfl_xor_sync(0xffffffffu, sum1, 1);
        sum1 += __shfl_xor_sync(0xffffffffu, sum1, 2);
        l_i[0] = l_i[0] * al0 + sum0;
        l_i[1] = l_i[1] * al1 + sum1;

#pragma unroll
        for (int f = 0; f < 8; f++) {
            accO[f][0] *= al0; accO[f][1] *= al0;
            accO[f][2] *= al1; accO[f][3] *= al1;
        }

        // ---- O += P V (2-term: ph*vh + ph*vl) ----
#pragma unroll
        for (int ks = 0; ks < 4; ks++) {
            const int f0 = 2 * ks, f1 = 2 * ks + 1;
            uint32_t ah[4];
            ah[0] = h2u(__floats2half2_rn(sf[f0][0], sf[f0][1]));
            ah[1] = h2u(__floats2half2_rn(sf[f0][2], sf[f0][3]));
            ah[2] = h2u(__floats2half2_rn(sf[f1][0], sf[f1][1]));
            ah[3] = h2u(__floats2half2_rn(sf[f1][2], sf[f1][3]));

            const int vrow = ks * 16 + vrow_l;
            uint32_t vh[4][4], vl[4][4];
#pragma unroll
            for (int g2 = 0; g2 < 4; g2++) {
                const int vg = 2 * g2 + gsel;
                const uint32_t va = kvb + (uint32_t)(vrow * 128) +
                                    (uint32_t)((vg ^ vswz) << 4);
                ldsm4t(vh[g2], ATT_VHo + va);
                ldsm4t(vl[g2], ATT_VLo + va);
            }
#pragma unroll
            for (int g2 = 0; g2 < 4; g2++) {
                mma_f16(accO[2 * g2],     ah, vh[g2][0], vh[g2][1]);
                mma_f16(accO[2 * g2 + 1], ah, vh[g2][2], vh[g2][3]);
            }
#pragma unroll
            for (int g2 = 0; g2 < 4; g2++) {
                mma_f16(accO[2 * g2],     ah, vl[g2][0], vl[g2][1]);
                mma_f16(accO[2 * g2 + 1], ah, vl[g2][2], vl[g2][3]);
            }
        }
    }

    // ---- epilogue: normalize + fp16 hi/lo split (feeds proj GEMM) ----
    const float inv0 = 1.f / l_i[0];
    const float inv1 = 1.f / l_i[1];
    const size_t r0 = rowbase + q0 + warp_m + (lane >> 2);
    const size_t r1 = r0 + 8;
    const int colb = h * 64 + (lane & 3) * 2;
#pragma unroll
    for (int f = 0; f < 8; f++) {
        float v00 = accO[f][0] * inv0, v01 = accO[f][1] * inv0;
        float v10 = accO[f][2] * inv1, v11 = accO[f][3] * inv1;
        __half h00 = __float2half_rn(v00), h01 = __float2half_rn(v01);
        __half h10 = __float2half_rn(v10), h11 = __float2half_rn(v11);
        __half l00 = __float2half_rn(v00 - __half2float(h00));
        __half l01 = __float2half_rn(v01 - __half2float(h01));
        __half l10 = __float2half_rn(v10 - __half2float(h10));
        __half l11 = __float2half_rn(v11 - __half2float(h11));
        const size_t o0 = r0 * 768 + colb + 8 * f;
        const size_t o1 = r1 * 768 + colb + 8 * f;
        *(ushort2*)(Ohi + o0) = make_ushort2(__half_as_ushort(h00), __half_as_ushort(h01));
        *(ushort2*)(Olo + o0) = make_ushort2(__half_as_ushort(l00), __half_as_ushort(l01));
        *(ushort2*)(Ohi + o1) = make_ushort2(__half_as_ushort(h10), __half_as_ushort(h11));
        *(ushort2*)(Olo + o1) = make_ushort2(__half_as_ushort(l10), __half_as_ushort(l11));
    }
}

// ================= launch =================
extern "C" void kernel_launch(void* const* d_in, const int* in_sizes, int n_in,
                              void* d_out, int out_size)
{
    const float* x      = (const float*)d_in[0];
    const float* x2     = (const float*)d_in[1];
    const float* qkv_w  = (const float*)d_in[2];
    const float* proj_w = (const float*)d_in[3];
    const float* proj_b = (const float*)d_in[4];
    float* out = (float*)d_out;

    __half *qkvh, *qkvl, *kv2h, *kv2l;
    __half *xhi, *xlo, *x2hi, *x2lo, *wqhi, *wqlo, *wphi, *wplo;
    __half *o1hi, *o1lo, *o2hi, *o2lo;
    cudaGetSymbolAddress((void**)&qkvh, g_qkvh);
    cudaGetSymbolAddress((void**)&qkvl, g_qkvl);
    cudaGetSymbolAddress((void**)&kv2h, g_kv2h);
    cudaGetSymbolAddress((void**)&kv2l, g_kv2l);
    cudaGetSymbolAddress((void**)&xhi,  g_xhi);
    cudaGetSymbolAddress((void**)&xlo,  g_xlo);
    cudaGetSymbolAddress((void**)&x2hi, g_x2hi);
    cudaGetSymbolAddress((void**)&x2lo, g_x2lo);
    cudaGetSymbolAddress((void**)&wqhi, g_wqhi);
    cudaGetSymbolAddress((void**)&wqlo, g_wqlo);
    cudaGetSymbolAddress((void**)&wphi, g_wphi);
    cudaGetSymbolAddress((void**)&wplo, g_wplo);
    cudaGetSymbolAddress((void**)&o1hi, g_o1hi);
    cudaGetSymbolAddress((void**)&o1lo, g_o1lo);
    cudaGetSymbolAddress((void**)&o2hi, g_o2hi);
    cudaGetSymbolAddress((void**)&o2lo, g_o2lo);

    cudaFuncSetAttribute(gemm_hmma, cudaFuncAttributeMaxDynamicSharedMemorySize, GEMM_SMEM);
    cudaFuncSetAttribute(attn_hmma, cudaFuncAttributeMaxDynamicSharedMemorySize, ATT_SMEM);

    const int M = 8192;

    {
        int n4 = 8192 * 768 / 4;
        split_f16<<<n4 / 256, 256>>>((const float4*)x,  (uint2*)xhi,  (uint2*)xlo,  n4);
        split_f16<<<n4 / 256, 256>>>((const float4*)x2, (uint2*)x2hi, (uint2*)x2lo, n4);
    }
    {
        int n4 = 2304 * 768 / 4;
        split_f16<<<n4 / 256, 256>>>((const float4*)qkv_w, (uint2*)wqhi, (uint2*)wqlo, n4);
    }
    {
        int n4 = 768 * 768 / 4;
        split_f16<<<n4 / 256, 256>>>((const float4*)proj_w, (uint2*)wphi, (uint2*)wplo, n4);
    }

    // QKV (x, 36 n-tiles) + KV2 (x2, 24 n-tiles); only Q columns 3-term
    gemm_hmma<<<dim3(60, M / 128), 256, GEMM_SMEM>>>(
        xhi, xlo, x2hi, x2lo, wqhi, wqlo,
        nullptr, nullptr, nullptr,
        qkvh, qkvl, kv2h, kv2l,
        36, 2304, 1536, 768, /*vs1=*/768, /*vs2=*/0, 1);

    // both attention branches in one launch (z = branch)
    attn_hmma<<<dim3(8, 96, 2), 256, ATT_SMEM>>>(
        qkvh, 2304,
        qkvh + 768, qkvl + 768, qkvh + 1536, qkvl + 1536, 2304,
        kv2h, kv2l, kv2h + 768, kv2l + 768, 1536,
        o1hi, o1lo, o2hi, o2lo);

    // both output projections (+bias), all 2-term
    gemm_hmma<<<dim3(24, M / 128), 256, GEMM_SMEM>>>(
        o1hi, o1lo, o2hi, o2lo, wphi, wplo,
        out, out + (size_t)M * 768, proj_b,
        nullptr, nullptr, nullptr, nullptr,
        12, 768, 768, 0, /*vs1=*/0, /*vs2=*/0, 0);
}

// round 17
// speedup vs baseline: 1.5546x; 1.0945x over previous
#include <cuda_runtime.h>
#include <cuda_fp16.h>
#include <cstdint>

// ================= scratch (no allocations allowed) =================
__device__ __align__(256) __half g_qkvh[8192 * 2304], g_qkvl[8192 * 2304]; // q|k|v fp16 hi/lo
__device__ __align__(256) __half g_kv2h[8192 * 1536], g_kv2l[8192 * 1536]; // k2|v2 fp16 hi/lo

__device__ __align__(256) __half g_xhi[8192 * 768];
__device__ __align__(256) __half g_x2hi[8192 * 768];
__device__ __align__(256) __half g_wqhi[2304 * 768], g_wqlo[2304 * 768];
__device__ __align__(256) __half g_wphi[768 * 768],  g_wplo[768 * 768];
__device__ __align__(256) __half g_o1hi[8192 * 768];
__device__ __align__(256) __half g_o2hi[8192 * 768];

// ================= helpers =================
__device__ __forceinline__ void cp16(uint32_t s, const void* g) {
    asm volatile("cp.async.cg.shared.global [%0], [%1], 16;" :: "r"(s), "l"(g));
}

__device__ __forceinline__ void ldsm4(uint32_t* r, uint32_t addr) {
    asm volatile("ldmatrix.sync.aligned.m8n8.x4.shared.b16 {%0,%1,%2,%3}, [%4];"
                 : "=r"(r[0]), "=r"(r[1]), "=r"(r[2]), "=r"(r[3]) : "r"(addr));
}

__device__ __forceinline__ void ldsm4t(uint32_t* r, uint32_t addr) {
    asm volatile("ldmatrix.sync.aligned.m8n8.x4.trans.shared.b16 {%0,%1,%2,%3}, [%4];"
                 : "=r"(r[0]), "=r"(r[1]), "=r"(r[2]), "=r"(r[3]) : "r"(addr));
}

__device__ __forceinline__ void mma_f16(float* c, const uint32_t* a,
                                        uint32_t b0, uint32_t b1) {
    asm volatile(
        "mma.sync.aligned.m16n8k16.row.col.f32.f16.f16.f32 "
        "{%0,%1,%2,%3}, {%4,%5,%6,%7}, {%8,%9}, {%0,%1,%2,%3};"
        : "+f"(c[0]), "+f"(c[1]), "+f"(c[2]), "+f"(c[3])
        : "r"(a[0]), "r"(a[1]), "r"(a[2]), "r"(a[3]), "r"(b0), "r"(b1));
}

__device__ __forceinline__ uint32_t h2u(__half2 h) { return *(uint32_t*)&h; }

// ================= fp16 splits =================
__global__ __launch_bounds__(256)
void split_f16(const float4* __restrict__ src, uint2* __restrict__ hi,
               uint2* __restrict__ lo, int n4)
{
    int i = blockIdx.x * blockDim.x + threadIdx.x;
    if (i >= n4) return;
    float4 v = src[i];
    float f[4] = {v.x, v.y, v.z, v.w};
    uint32_t hh[2], ll[2];
#pragma unroll
    for (int j = 0; j < 2; j++) {
        __half2 h = __floats2half2_rn(f[2 * j], f[2 * j + 1]);
        float2 hf = __half22float2(h);
        __half2 l = __floats2half2_rn(f[2 * j] - hf.x, f[2 * j + 1] - hf.y);
        hh[j] = h2u(h);
        ll[j] = h2u(l);
    }
    hi[i] = make_uint2(hh[0], hh[1]);
    lo[i] = make_uint2(ll[0], ll[1]);
}

// hi-only conversion (A operands: x, x2)
__global__ __launch_bounds__(256)
void conv_f16(const float4* __restrict__ src, uint2* __restrict__ hi, int n4)
{
    int i = blockIdx.x * blockDim.x + threadIdx.x;
    if (i >= n4) return;
    float4 v = src[i];
    hi[i] = make_uint2(h2u(__floats2half2_rn(v.x, v.y)),
                       h2u(__floats2half2_rn(v.z, v.w)));
}

// ========= HMMA fp16 2-term GEMM: 128x64 tile, 2 CTAs/SM, dual A-stream =====
// C = A_hi * (B_hi + B_lo). bx < nx1 -> stream 1, else stream 2.
#define GT_AH 0
#define GT_BH 16384
#define GT_BL 24576
#define G_STAGE 32768
#define GEMM_SMEM (2 * G_STAGE)

__global__ __launch_bounds__(256, 2)
void gemm_hmma(const __half* __restrict__ A1hi, const __half* __restrict__ A2hi,
               const __half* __restrict__ Bhi, const __half* __restrict__ Blo,
               float* __restrict__ C1, float* __restrict__ C2, const float* __restrict__ bias,
               __half* __restrict__ H1h, __half* __restrict__ H1l,
               __half* __restrict__ H2h, __half* __restrict__ H2l,
               int nx1, int N1, int N2, int woff2, int mode)
{
    extern __shared__ __align__(1024) char smem[];
    const uint32_t sb = (uint32_t)__cvta_generic_to_shared(smem);
    const int t = threadIdx.x;
    const int wid = t >> 5, lane = t & 31;
    const int m0 = blockIdx.y * 128;
    const int K = 768, NC = 12;

    const int s2 = (int)blockIdx.x >= nx1;
    const int bx = s2 ? (int)blockIdx.x - nx1 : (int)blockIdx.x;
    const int n0 = bx * 64;
    const int N = s2 ? N2 : N1;
    const int woff = s2 ? woff2 : 0;

    const int warp_m = (wid >> 1) * 32;
    const int warp_n = (wid & 1) * 32;

    float acc[2][4][4];
#pragma unroll
    for (int i = 0; i < 2; i++)
#pragma unroll
        for (int j = 0; j < 4; j++)
#pragma unroll
            for (int v = 0; v < 4; v++) acc[i][j][v] = 0.f;

    const __half* Ah = (s2 ? A2hi : A1hi) + (size_t)m0 * K;
    const __half* Bh = Bhi + (size_t)(woff + n0) * K;
    const __half* Bl = Blo + (size_t)(woff + n0) * K;

    auto load_chunk = [&](int c, int st) {
        const int kc = c * 64;
        const uint32_t base = sb + st * G_STAGE;
#pragma unroll
        for (int i = 0; i < 4; i++) {            // A: 1024 granules, 4/thread
            const int gi = t + i * 256;
            const int row = gi >> 3, g = gi & 7;
            const uint32_t loff = (uint32_t)(row * 128 + ((g ^ (row & 7)) << 4));
            cp16(base + GT_AH + loff, Ah + (size_t)row * K + kc + g * 8);
        }
#pragma unroll
        for (int i = 0; i < 2; i++) {            // B: 512 granules, 2/thread
            const int gi = t + i * 256;
            const int row = gi >> 3, g = gi & 7;
            const uint32_t loff = (uint32_t)(row * 128 + ((g ^ (row & 7)) << 4));
            const size_t goff = (size_t)row * K + kc + g * 8;
            cp16(base + GT_BH + loff, Bh + goff);
            cp16(base + GT_BL + loff, Bl + goff);
        }
        asm volatile("cp.async.commit_group;");
    };

    const int fr   = lane & 15;
    const int half = lane >> 4;
    const int arow = warp_m + fr;
    const int brow = warp_n + fr;
    const int aswz = arow & 7;
    const int bswz = brow & 7;
    const uint32_t arow_off = (uint32_t)(arow * 128);
    const uint32_t brow_off = (uint32_t)(brow * 128);

    load_chunk(0, 0);

    for (int c = 0; c < NC; ++c) {
        const int st = c & 1;
        if (c + 1 < NC) {
            load_chunk(c + 1, st ^ 1);
            asm volatile("cp.async.wait_group 1;");
        } else {
            asm volatile("cp.async.wait_group 0;");
        }
        __syncthreads();

        const uint32_t base = sb + st * G_STAGE;
#pragma unroll
        for (int kk = 0; kk < 4; kk++) {
            const int kg = kk * 2 + half;
            const uint32_t aoff = arow_off + (uint32_t)((kg ^ aswz) << 4);
            const uint32_t boff = brow_off + (uint32_t)((kg ^ bswz) << 4);

            uint32_t ah[2][4], bh[2][4], bl[2][4];
#pragma unroll
            for (int mi = 0; mi < 2; mi++)
                ldsm4(ah[mi], base + GT_AH + aoff + mi * (16 * 128));
#pragma unroll
            for (int bj = 0; bj < 2; bj++) {
                ldsm4(bh[bj], base + GT_BH + boff + bj * (16 * 128));
                ldsm4(bl[bj], base + GT_BL + boff + bj * (16 * 128));
            }
#pragma unroll
            for (int mi = 0; mi < 2; mi++)
#pragma unroll
                for (int bj = 0; bj < 2; bj++) {
                    mma_f16(acc[mi][bj * 2],     ah[mi], bh[bj][0], bh[bj][2]);
                    mma_f16(acc[mi][bj * 2 + 1], ah[mi], bh[bj][1], bh[bj][3]);
                }
#pragma unroll
            for (int mi = 0; mi < 2; mi++)
#pragma unroll
                for (int bj = 0; bj < 2; bj++) {
                    mma_f16(acc[mi][bj * 2],     ah[mi], bl[bj][0], bl[bj][2]);
                    mma_f16(acc[mi][bj * 2 + 1], ah[mi], bl[bj][1], bl[bj][3]);
                }
        }
        __syncthreads();
    }

    float* C = s2 ? C2 : C1;
    __half* Hh = s2 ? H2h : H1h;
    __half* Hl = s2 ? H2l : H1l;
#pragma unroll
    for (int mi = 0; mi < 2; mi++) {
        const int r = m0 + warp_m + mi * 16 + (lane >> 2);
#pragma unroll
        for (int j = 0; j < 4; j++) {
            const int col = n0 + warp_n + j * 8 + (lane & 3) * 2;
            float v00 = acc[mi][j][0], v01 = acc[mi][j][1];
            float v10 = acc[mi][j][2], v11 = acc[mi][j][3];
            if (mode == 0) {
                const float b0 = bias[col], b1 = bias[col + 1];
                *(float2*)(C + (size_t)r * N + col)       = make_float2(v00 + b0, v01 + b1);
                *(float2*)(C + (size_t)(r + 8) * N + col) = make_float2(v10 + b0, v11 + b1);
            } else {
                __half h00 = __float2half_rn(v00), h01 = __float2half_rn(v01);
                __half h10 = __float2half_rn(v10), h11 = __float2half_rn(v11);
                __half l00 = __float2half_rn(v00 - __half2float(h00));
                __half l01 = __float2half_rn(v01 - __half2float(h01));
                __half l10 = __float2half_rn(v10 - __half2float(h10));
                __half l11 = __float2half_rn(v11 - __half2float(h11));
                const size_t o0 = (size_t)r * N + col;
                const size_t o1 = (size_t)(r + 8) * N + col;
                *(ushort2*)(Hh + o0) = make_ushort2(__half_as_ushort(h00), __half_as_ushort(h01));
                *(ushort2*)(Hl + o0) = make_ushort2(__half_as_ushort(l00), __half_as_ushort(l01));
                *(ushort2*)(Hh + o1) = make_ushort2(__half_as_ushort(h10), __half_as_ushort(h11));
                *(ushort2*)(Hl + o1) = make_ushort2(__half_as_ushort(l10), __half_as_ushort(l11));
            }
        }
    }
}

// == HMMA flash attention: 2 CTAs/SM, merged branches, QK+PV 2-term ===========
// QK = qh*(kh+kl). PV = ph*(vh+vl). Output: hi only (feeds proj A-side).
#define ATT_QH 0
#define ATT_KV 32768
#define ATT_KV_STAGE 32768
#define ATT_SMEM 98304
#define ATT_KHo 0
#define ATT_KLo 8192
#define ATT_VHo 16384
#define ATT_VLo 24576

__global__ __launch_bounds__(256, 2)
void attn_hmma(const __half* __restrict__ Qh, int ldq,
               const __half* __restrict__ K1h, const __half* __restrict__ K1l,
               const __half* __restrict__ V1h, const __half* __restrict__ V1l, int ld1,
               const __half* __restrict__ K2h, const __half* __restrict__ K2l,
               const __half* __restrict__ V2h, const __half* __restrict__ V2l, int ld2,
               __half* __restrict__ O1hi, __half* __restrict__ O2hi)
{
    extern __shared__ __align__(1024) char smem[];
    const uint32_t sb = (uint32_t)__cvta_generic_to_shared(smem);
    const int t = threadIdx.x;
    const int lane = t & 31, wid = t >> 5;
    const int warp_m = wid * 16;
    const int bh = blockIdx.y;
    const int br = blockIdx.z;
    const int b = bh / 12, h = bh % 12;
    const int q0 = blockIdx.x * 128;
    const size_t rowbase = (size_t)b * 1024;

    const int ldkv = br ? ld2 : ld1;
    const __half* Kph = (br ? K2h : K1h) + rowbase * ldkv + h * 64;
    const __half* Kpl = (br ? K2l : K1l) + rowbase * ldkv + h * 64;
    const __half* Vph = (br ? V2h : V1h) + rowbase * ldkv + h * 64;
    const __half* Vpl = (br ? V2l : V1l) + rowbase * ldkv + h * 64;
    __half* Ohi = br ? O2hi : O1hi;
    const __half* Qph = Qh + (rowbase + q0) * ldq + h * 64;

    auto load_kv = [&](int c, int st) {
        const int k0 = c * 64;
        const uint32_t base = sb + ATT_KV + st * ATT_KV_STAGE;
#pragma unroll
        for (int i = 0; i < 8; i++) {
            const int idx = t + i * 256;
            const int sel = i >> 1;             // 0:KH 1:KL 2:VH 3:VL
            const int r = (idx >> 3) & 63, g = idx & 7;
            const __half* src = (sel == 0 ? Kph : sel == 1 ? Kpl
                                 : sel == 2 ? Vph : Vpl) + (size_t)(k0 + r) * ldkv + g * 8;
            const uint32_t off = base + sel * 8192 +
                                 (uint32_t)(r * 128 + ((g ^ (r & 7)) << 4));
            cp16(off, src);
        }
    };

    // prologue: Q hi (1024 granules) + chunk 0
#pragma unroll
    for (int i = 0; i < 4; i++) {
        const int idx = t + i * 256;
        const int r = idx >> 3, g = idx & 7;
        const __half* src = Qph + (size_t)r * ldq + g * 8;
        const uint32_t off = sb + ATT_QH +
                             (uint32_t)(r * 128 + ((g ^ (r & 7)) << 4));
        cp16(off, src);
    }
    load_kv(0, 0);
    asm volatile("cp.async.commit_group;");

    float m_i[2], l_i[2], accO[8][4];
    m_i[0] = m_i[1] = -1e30f;
    l_i[0] = l_i[1] = 0.f;
#pragma unroll
    for (int f = 0; f < 8; f++)
#pragma unroll
        for (int v = 0; v < 4; v++) accO[f][v] = 0.f;

    const int f16  = lane & 15;
    const int gsel = lane >> 4;
    const int qrow = warp_m + f16;
    const uint32_t q_off = (uint32_t)(qrow * 128);
    const int qswz = qrow & 7;
    const int kswz = f16 & 7;
    const int vrow_l = (lane & 7) + 8 * ((lane >> 3) & 1);
    const int vswz = vrow_l & 7;

    for (int c = 0; c < 16; ++c) {
        const int st = c & 1;
        asm volatile("cp.async.wait_group 0;");
        __syncthreads();
        const uint32_t kvb = sb + ATT_KV + st * ATT_KV_STAGE;

        float sf[8][4];
#pragma unroll
        for (int f = 0; f < 8; f++)
#pragma unroll
            for (int v = 0; v < 4; v++) sf[f][v] = 0.f;

#pragma unroll
        for (int ks = 0; ks < 4; ks++) {
            const int kg = 2 * ks + gsel;
            uint32_t qh[4];
            const uint32_t qa = sb + q_off + (uint32_t)((kg ^ qswz) << 4);
            ldsm4(qh, ATT_QH + qa);

            uint32_t kh[4][4], kl[4][4];
#pragma unroll
            for (int np = 0; np < 4; np++) {
                const uint32_t ka = kvb + (uint32_t)((np * 16 + f16) * 128) +
                                    (uint32_t)((kg ^ kswz) << 4);
                ldsm4(kh[np], ATT_KHo + ka);
                ldsm4(kl[np], ATT_KLo + ka);
            }
#pragma unroll
            for (int np = 0; np < 4; np++) {
                mma_f16(sf[2 * np],     qh, kh[np][0], kh[np][2]);
                mma_f16(sf[2 * np + 1], qh, kh[np][1], kh[np][3]);
            }
#pragma unroll
            for (int np = 0; np < 4; np++) {
                mma_f16(sf[2 * np],     qh, kl[np][0], kl[np][2]);
                mma_f16(sf[2 * np + 1], qh, kl[np][1], kl[np][3]);
            }
        }

        if (c + 1 < 16) {
            load_kv(c + 1, st ^ 1);
            asm volatile("cp.async.commit_group;");
        }

        float mx0 = -1e30f, mx1 = -1e30f;
#pragma unroll
        for (int f = 0; f < 8; f++) {
            sf[f][0] *= 0.125f; sf[f][1] *= 0.125f;
            sf[f][2] *= 0.125f; sf[f][3] *= 0.125f;
            mx0 = fmaxf(mx0, fmaxf(sf[f][0], sf[f][1]));
            mx1 = fmaxf(mx1, fmaxf(sf[f][2], sf[f][3]));
        }
        mx0 = fmaxf(mx0, __shfl_xor_sync(0xffffffffu, mx0, 1));
        mx0 = fmaxf(mx0, __shfl_xor_sync(0xffffffffu, mx0, 2));
        mx1 = fmaxf(mx1, __shfl_xor_sync(0xffffffffu, mx1, 1));
        mx1 = fmaxf(mx1, __shfl_xor_sync(0xffffffffu, mx1, 2));

        const float mn0 = fmaxf(m_i[0], mx0);
        const float mn1 = fmaxf(m_i[1], mx1);
        const float al0 = __expf(m_i[0] - mn0);
        const float al1 = __expf(m_i[1] - mn1);
        m_i[0] = mn0; m_i[1] = mn1;

        float sum0 = 0.f, sum1 = 0.f;
#pragma unroll
        for (int f = 0; f < 8; f++) {
            sf[f][0] = __expf(sf[f][0] - mn0);
            sf[f][1] = __expf(sf[f][1] - mn0);
            sf[f][2] = __expf(sf[f][2] - mn1);
            sf[f][3] = __expf(sf[f][3] - mn1);
            sum0 += sf[f][0] + sf[f][1];
            sum1 += sf[f][2] + sf[f][3];
        }
        sum0 += __shfl_xor_sync(0xffffffffu, sum0, 1);
        sum0 += __shfl_xor_sync(0xffffffffu, sum0, 2);
        sum1 += __shfl_xor_sync(0xffffffffu, sum1, 1);
        sum1 += __shfl_xor_sync(0xffffffffu, sum1, 2);
        l_i[0] = l_i[0] * al0 + sum0;
        l_i[1] = l_i[1] * al1 + sum1;

#pragma unroll
        for (int f = 0; f < 8; f++) {
            accO[f][0] *= al0; accO[f][1] *= al0;
            accO[f][2] *= al1; accO[f][3] *= al1;
        }

        // ---- O += P V (2-term: ph*vh + ph*vl) ----
#pragma unroll
        for (int ks = 0; ks < 4; ks++) {
            const int f0 = 2 * ks, f1 = 2 * ks + 1;
            uint32_t ah[4];
            ah[0] = h2u(__floats2half2_rn(sf[f0][0], sf[f0][1]));
            ah[1] = h2u(__floats2half2_rn(sf[f0][2], sf[f0][3]));
            ah[2] = h2u(__floats2half2_rn(sf[f1][0], sf[f1][1]));
            ah[3] = h2u(__floats2half2_rn(sf[f1][2], sf[f1][3]));

            const int vrow = ks * 16 + vrow_l;
            uint32_t vh[4][4], vl[4][4];
#pragma unroll
            for (int g2 = 0; g2 < 4; g2++) {
                const int vg = 2 * g2 + gsel;
                const uint32_t va = kvb + (uint32_t)(vrow * 128) +
                                    (uint32_t)((vg ^ vswz) << 4);
                ldsm4t(vh[g2], ATT_VHo + va);
                ldsm4t(vl[g2], ATT_VLo + va);
            }
#pragma unroll
            for (int g2 = 0; g2 < 4; g2++) {
                mma_f16(accO[2 * g2],     ah, vh[g2][0], vh[g2][1]);
                mma_f16(accO[2 * g2 + 1], ah, vh[g2][2], vh[g2][3]);
            }
#pragma unroll
            for (int g2 = 0; g2 < 4; g2++) {
                mma_f16(accO[2 * g2],     ah, vl[g2][0], vl[g2][1]);
                mma_f16(accO[2 * g2 + 1], ah, vl[g2][2], vl[g2][3]);
            }
        }
    }

    // ---- epilogue: normalize + fp16 hi only (feeds proj GEMM A-side) ----
    const float inv0 = 1.f / l_i[0];
    const float inv1 = 1.f / l_i[1];
    const size_t r0 = rowbase + q0 + warp_m + (lane >> 2);
    const size_t r1 = r0 + 8;
    const int colb = h * 64 + (lane & 3) * 2;
#pragma unroll
    for (int f = 0; f < 8; f++) {
        const size_t o0 = r0 * 768 + colb + 8 * f;
        const size_t o1 = r1 * 768 + colb + 8 * f;
        *(uint32_t*)(Ohi + o0) = h2u(__floats2half2_rn(accO[f][0] * inv0, accO[f][1] * inv0));
        *(uint32_t*)(Ohi + o1) = h2u(__floats2half2_rn(accO[f][2] * inv1, accO[f][3] * inv1));
    }
}

// ================= launch =================
extern "C" void kernel_launch(void* const* d_in, const int* in_sizes, int n_in,
                              void* d_out, int out_size)
{
    const float* x      = (const float*)d_in[0];
    const float* x2     = (const float*)d_in[1];
    const float* qkv_w  = (const float*)d_in[2];
    const float* proj_w = (const float*)d_in[3];
    const float* proj_b = (const float*)d_in[4];
    float* out = (float*)d_out;

    __half *qkvh, *qkvl, *kv2h, *kv2l;
    __half *xhi, *x2hi, *wqhi, *wqlo, *wphi, *wplo;
    __half *o1hi, *o2hi;
    cudaGetSymbolAddress((void**)&qkvh, g_qkvh);
    cudaGetSymbolAddress((void**)&qkvl, g_qkvl);
    cudaGetSymbolAddress((void**)&kv2h, g_kv2h);
    cudaGetSymbolAddress((void**)&kv2l, g_kv2l);
    cudaGetSymbolAddress((void**)&xhi,  g_xhi);
    cudaGetSymbolAddress((void**)&x2hi, g_x2hi);
    cudaGetSymbolAddress((void**)&wqhi, g_wqhi);
    cudaGetSymbolAddress((void**)&wqlo, g_wqlo);
    cudaGetSymbolAddress((void**)&wphi, g_wphi);
    cudaGetSymbolAddress((void**)&wplo, g_wplo);
    cudaGetSymbolAddress((void**)&o1hi, g_o1hi);
    cudaGetSymbolAddress((void**)&o2hi, g_o2hi);

    cudaFuncSetAttribute(gemm_hmma, cudaFuncAttributeMaxDynamicSharedMemorySize, GEMM_SMEM);
    cudaFuncSetAttribute(attn_hmma, cudaFuncAttributeMaxDynamicSharedMemorySize, ATT_SMEM);

    const int M = 8192;

    {
        int n4 = 8192 * 768 / 4;
        conv_f16<<<n4 / 256, 256>>>((const float4*)x,  (uint2*)xhi,  n4);
        conv_f16<<<n4 / 256, 256>>>((const float4*)x2, (uint2*)x2hi, n4);
    }
    {
        int n4 = 2304 * 768 / 4;
        split_f16<<<n4 / 256, 256>>>((const float4*)qkv_w, (uint2*)wqhi, (uint2*)wqlo, n4);
    }
    {
        int n4 = 768 * 768 / 4;
        split_f16<<<n4 / 256, 256>>>((const float4*)proj_w, (uint2*)wphi, (uint2*)wplo, n4);
    }

    // QKV (x, 36 n-tiles) + KV2 (x2, 24 n-tiles); all 2-term, fp16 hi/lo out
    gemm_hmma<<<dim3(60, M / 128), 256, GEMM_SMEM>>>(
        xhi, x2hi, wqhi, wqlo,
        nullptr, nullptr, nullptr,
        qkvh, qkvl, kv2h, kv2l,
        36, 2304, 1536, 768, 1);

    // both attention branches in one launch (z = branch); O hi only
    attn_hmma<<<dim3(8, 96, 2), 256, ATT_SMEM>>>(
        qkvh, 2304,
        qkvh + 768, qkvl + 768, qkvh + 1536, qkvl + 1536, 2304,
        kv2h, kv2l, kv2h + 768, kv2l + 768, 1536,
        o1hi, o2hi);

    // both output projections (+bias), 2-term
    gemm_hmma<<<dim3(24, M / 128), 256, GEMM_SMEM>>>(
        o1hi, o2hi, wphi, wplo,
        out, out + (size_t)M * 768, proj_b,
        nullptr, nullptr, nullptr, nullptr,
        12, 768, 768, 0, 0);
}